// round 5
// baseline (speedup 1.0000x reference)
#include <cuda_runtime.h>
#include <math.h>

#define N_NODES 65536
#define NG      256
#define NPG     256
#define DD      128
#define EE      1048576
#define TRIU    8256
#define FC1N    1024
#define FC2N    256
#define CLSN    10

// ---------------- device scratch (no allocations allowed) ----------------
__device__ float  g_h[N_NODES * DD];
__device__ float  g_y[N_NODES * DD];
__device__ float  g_sum[DD];
__device__ float  g_sumsq[DD];
__device__ float  g_scale[DD];
__device__ float  g_shift[DD];
__device__ double g_nrm[NG];
__device__ double g_X64a[NG * DD * DD];
__device__ double g_X64b[NG * DD * DD];
__device__ double g_Y64[NG * DD * DD];
__device__ double g_T64[NG * DD * DD];
__device__ float  g_X32a[NG * DD * DD];
__device__ float  g_X32b[NG * DD * DD];
__device__ float  g_Y32[NG * DD * DD];
__device__ float  g_T32[NG * DD * DD];
__device__ float  g_pooled[NG * TRIU];
__device__ float  g_z1[NG * FC1N];
__device__ float  g_z2[NG * FC2N];

// ---------------- init ----------------------------------------------------
__global__ void k_init(const float* __restrict__ x, const float* __restrict__ eps_p) {
    size_t i = (size_t)blockIdx.x * blockDim.x + threadIdx.x;
    size_t stride = (size_t)gridDim.x * blockDim.x;
    float e = 1.0f + *eps_p;
    for (size_t j = i; j < (size_t)N_NODES * DD; j += stride) g_h[j] = e * x[j];
    for (size_t j = i; j < (size_t)NG * FC1N; j += stride) g_z1[j] = 0.f;
    for (size_t j = i; j < (size_t)NG * FC2N; j += stride) g_z2[j] = 0.f;
    if (i < DD) { g_sum[i] = 0.f; g_sumsq[i] = 0.f; }
    if (i < NG) g_nrm[i] = 0.0;
}

// ---------------- edge aggregation: atomic scatter-add --------------------
__global__ void k_edge(const float* __restrict__ x, const int* __restrict__ ei) {
    long long tid = (long long)blockIdx.x * 256 + threadIdx.x;
    int f = (int)(tid & 127);
    int e = (int)(tid >> 7);
    int s = ei[e], d = ei[EE + e];
    atomicAdd(&g_h[(size_t)d * DD + f], x[(size_t)s * DD + f]);
}

// ---------------- node GEMMs: 128x128 tile, 256 threads, 8x8/thread ------
template <int MODE>
__global__ void k_gemm_nodes(const float* __restrict__ W,
                             const float* __restrict__ bias,
                             float* __restrict__ outp) {
    __shared__ float As[16 * 132];
    __shared__ float Bs[16 * 128];
    __shared__ float ssc[DD], ssh[DD];
    const float* A = (MODE == 0) ? g_h : g_y;
    float* O = (MODE == 0) ? g_y : outp;
    int t = threadIdx.x;
    if (MODE == 1) {
        if (t < DD) { ssc[t] = g_scale[t]; ssh[t] = g_shift[t]; }
        __syncthreads();
    }
    int tx = t & 15, ty = t >> 4;
    int row0 = blockIdx.x * 128;
    float acc[8][8];
#pragma unroll
    for (int i = 0; i < 8; i++)
#pragma unroll
        for (int j = 0; j < 8; j++) acc[i][j] = 0.f;

    for (int k0 = 0; k0 < DD; k0 += 16) {
#pragma unroll
        for (int ld = 0; ld < 2; ld++) {
            int l = t + ld * 256;
            int row = l >> 2, c4 = l & 3;
            float4 a = *(const float4*)(A + (size_t)(row0 + row) * DD + k0 + c4 * 4);
            if (MODE == 1) {
                int kb = k0 + c4 * 4;
                a.x = fmaxf(fmaf(a.x, ssc[kb + 0], ssh[kb + 0]), 0.f);
                a.y = fmaxf(fmaf(a.y, ssc[kb + 1], ssh[kb + 1]), 0.f);
                a.z = fmaxf(fmaf(a.z, ssc[kb + 2], ssh[kb + 2]), 0.f);
                a.w = fmaxf(fmaf(a.w, ssc[kb + 3], ssh[kb + 3]), 0.f);
            }
            As[(c4 * 4 + 0) * 132 + row] = a.x;
            As[(c4 * 4 + 1) * 132 + row] = a.y;
            As[(c4 * 4 + 2) * 132 + row] = a.z;
            As[(c4 * 4 + 3) * 132 + row] = a.w;
        }
#pragma unroll
        for (int ld = 0; ld < 2; ld++) {
            int l = t + ld * 256;
            int kk = l >> 5, n4 = l & 31;
            *(float4*)(Bs + kk * 128 + n4 * 4) =
                *(const float4*)(W + (size_t)(k0 + kk) * DD + n4 * 4);
        }
        __syncthreads();
#pragma unroll
        for (int kk = 0; kk < 16; kk++) {
            float av[8], bv[8];
            *(float4*)av       = *(float4*)(As + kk * 132 + ty * 8);
            *(float4*)(av + 4) = *(float4*)(As + kk * 132 + ty * 8 + 4);
            *(float4*)bv       = *(float4*)(Bs + kk * 128 + tx * 8);
            *(float4*)(bv + 4) = *(float4*)(Bs + kk * 128 + tx * 8 + 4);
#pragma unroll
            for (int i = 0; i < 8; i++)
#pragma unroll
                for (int j = 0; j < 8; j++) acc[i][j] = fmaf(av[i], bv[j], acc[i][j]);
        }
        __syncthreads();
    }
#pragma unroll
    for (int i = 0; i < 8; i++) {
        int row = row0 + ty * 8 + i;
#pragma unroll
        for (int j4 = 0; j4 < 2; j4++) {
            int c = tx * 8 + j4 * 4;
            float4 o;
            o.x = acc[i][j4 * 4 + 0]; o.y = acc[i][j4 * 4 + 1];
            o.z = acc[i][j4 * 4 + 2]; o.w = acc[i][j4 * 4 + 3];
            if (MODE == 1) {
                o.x += bias[c + 0]; o.y += bias[c + 1];
                o.z += bias[c + 2]; o.w += bias[c + 3];
            }
            *(float4*)(O + (size_t)row * DD + c) = o;
        }
    }
}

// ---------------- BN stats over all nodes ---------------------------------
__global__ void k_stats() {
    __shared__ float sS[256], sQ[256];
    int t = threadIdx.x;
    int col = t & 127, half = t >> 7;
    int r0 = blockIdx.x * 256;
    float s = 0.f, q = 0.f;
    for (int r = r0 + half; r < r0 + 256; r += 2) {
        float v = g_y[(size_t)r * DD + col];
        s += v; q += v * v;
    }
    sS[t] = s; sQ[t] = q;
    __syncthreads();
    if (t < 128) {
        atomicAdd(&g_sum[col], sS[t] + sS[t + 128]);
        atomicAdd(&g_sumsq[col], sQ[t] + sQ[t + 128]);
    }
}

__global__ void k_bnfin(const float* __restrict__ g0, const float* __restrict__ be0) {
    int c = threadIdx.x;
    float m = g_sum[c] * (1.f / (float)N_NODES);
    float var = g_sumsq[c] * (1.f / (float)N_NODES) - m * m;
    float sc = rsqrtf(var + 1e-5f) * g0[c];
    g_scale[c] = sc;
    g_shift[c] = be0[c] - m * sc;
}

// ---------------- Gram in fp64: B = Hg^T Hg - I, plus ||B||_F^2 ------------
__global__ void k_gram64(const float* __restrict__ hidden) {
    __shared__ float sA[32 * 65];
    __shared__ float sB[32 * 65];
    int g = blockIdx.z;
    int r0 = blockIdx.y * 64, c0 = blockIdx.x * 64;
    int t = threadIdx.x, tx = t & 15, ty = t >> 4;
    const float* Hg = hidden + (size_t)g * NPG * DD;
    double acc[4][4];
#pragma unroll
    for (int i = 0; i < 4; i++)
#pragma unroll
        for (int j = 0; j < 4; j++) acc[i][j] = 0.0;

    for (int n0 = 0; n0 < NPG; n0 += 32) {
#pragma unroll
        for (int ld = 0; ld < 8; ld++) {
            int l = t + ld * 256;
            int n = l >> 6, cidx = l & 63;
            sA[n * 65 + cidx] = Hg[(size_t)(n0 + n) * DD + r0 + cidx];
            sB[n * 65 + cidx] = Hg[(size_t)(n0 + n) * DD + c0 + cidx];
        }
        __syncthreads();
#pragma unroll 4
        for (int nn = 0; nn < 32; nn++) {
            double av[4], bv[4];
#pragma unroll
            for (int i = 0; i < 4; i++) av[i] = (double)sA[nn * 65 + ty + 16 * i];
#pragma unroll
            for (int j = 0; j < 4; j++) bv[j] = (double)sB[nn * 65 + tx + 16 * j];
#pragma unroll
            for (int i = 0; i < 4; i++)
#pragma unroll
                for (int j = 0; j < 4; j++) acc[i][j] = fma(av[i], bv[j], acc[i][j]);
        }
        __syncthreads();
    }
    double nrm = 0.0;
    double* Bg = g_X64a + (size_t)g * DD * DD;
#pragma unroll
    for (int i = 0; i < 4; i++)
#pragma unroll
        for (int j = 0; j < 4; j++) {
            int gi = r0 + ty + 16 * i, gj = c0 + tx + 16 * j;
            double v = acc[i][j] - (gi == gj ? 1.0 : 0.0);
            Bg[(size_t)gi * DD + gj] = v;
            nrm = fma(v, v, nrm);
        }
    // warp reduce + atomic
    for (int o = 16; o; o >>= 1) nrm += __shfl_xor_sync(0xffffffffu, nrm, o);
    if ((t & 31) == 0) atomicAdd(&g_nrm[g], nrm);
}

// ---------------- scale X0 = B / ||B||_F ----------------------------------
__global__ void k_scale64() {
    size_t i = (size_t)blockIdx.x * 256 + threadIdx.x;
    size_t stride = (size_t)gridDim.x * 256;
    for (size_t j = i; j < (size_t)NG * DD * DD; j += stride) {
        int g = (int)(j >> 14);
        g_X64a[j] *= rsqrt(g_nrm[g]);
    }
}

// ---------------- batched GEMM: OUT = A * (alpha*I + beta*B1 + gamma*B2) ---
template <typename T>
__global__ void k_bgemm(const T* __restrict__ A, const T* __restrict__ B1,
                        const T* __restrict__ B2, T* __restrict__ OUT,
                        double alphaD, double betaD, double gammaD) {
    __shared__ T As[16 * 65];
    __shared__ T Ms[16 * 64];
    int g = blockIdx.z;
    int r0 = blockIdx.y * 64, c0 = blockIdx.x * 64;
    size_t base = (size_t)g * DD * DD;
    const T* Ag = A + base;
    const T* B1g = B1 + base;
    const T* B2g = B2 ? B2 + base : (const T*)0;
    int t = threadIdx.x, tx = t & 15, ty = t >> 4;
    T alpha = (T)alphaD, beta = (T)betaD, gamma = (T)gammaD;
    T acc[4][4];
#pragma unroll
    for (int i = 0; i < 4; i++)
#pragma unroll
        for (int j = 0; j < 4; j++) acc[i][j] = (T)0;

    for (int k0 = 0; k0 < DD; k0 += 16) {
#pragma unroll
        for (int ld = 0; ld < 4; ld++) {
            int l = t + ld * 256;
            int row = l >> 4, kc = l & 15;
            As[kc * 65 + row] = Ag[(size_t)(r0 + row) * DD + k0 + kc];
        }
#pragma unroll
        for (int ld = 0; ld < 4; ld++) {
            int l = t + ld * 256;
            int kr = l >> 6, col = l & 63;
            int gk = k0 + kr, gc = c0 + col;
            T v = beta * B1g[(size_t)gk * DD + gc];
            if (B2g) v += gamma * B2g[(size_t)gk * DD + gc];
            if (gk == gc) v += alpha;
            Ms[kr * 64 + col] = v;
        }
        __syncthreads();
#pragma unroll 4
        for (int kk = 0; kk < 16; kk++) {
            T av[4], mv[4];
#pragma unroll
            for (int i = 0; i < 4; i++) av[i] = As[kk * 65 + ty + 16 * i];
#pragma unroll
            for (int j = 0; j < 4; j++) mv[j] = Ms[kk * 64 + tx + 16 * j];
#pragma unroll
            for (int i = 0; i < 4; i++)
#pragma unroll
                for (int j = 0; j < 4; j++) acc[i][j] += av[i] * mv[j];
        }
        __syncthreads();
    }
    T* Og = OUT + base;
#pragma unroll
    for (int i = 0; i < 4; i++)
#pragma unroll
        for (int j = 0; j < 4; j++)
            Og[(size_t)(r0 + ty + 16 * i) * DD + c0 + tx + 16 * j] = acc[i][j];
}

// ---------------- fp64 -> fp32 convert ------------------------------------
__global__ void k_cvt(const double* __restrict__ src) {
    size_t i = (size_t)blockIdx.x * 256 + threadIdx.x;
    size_t stride = (size_t)gridDim.x * 256;
    for (size_t j = i; j < (size_t)NG * DD * DD; j += stride)
        g_X32a[j] = (float)src[j];
}

// ---------------- pack projector P = (I + sign)/2, triu flatten ------------
__global__ void k_pack(const float* __restrict__ X) {
    int g = blockIdx.x, t = threadIdx.x;
    const float* Xg = X + (size_t)g * DD * DD;
    float* Pg = g_pooled + (size_t)g * TRIU;
    for (int idx = t; idx < DD * DD; idx += 256) {
        int i = idx >> 7, j = idx & 127;
        if (j >= i)
            Pg[i * 128 - (i * (i - 1)) / 2 + (j - i)] =
                0.5f * Xg[idx] + (i == j ? 0.5f : 0.f);
    }
}

// ---------------- generic FC GEMM: 64x64 tile, split-K via grid.z ---------
__global__ void k_fc(const float* __restrict__ A, const float* __restrict__ B,
                     float* __restrict__ Cm, int M, int Nn, int K) {
    __shared__ float As[16 * 68];
    __shared__ float Bs[16 * 64];
    int t = threadIdx.x;
    int tx = t & 15, ty = t >> 4;
    int c0 = blockIdx.x * 64, r0 = blockIdx.y * 64;
    int klen = K / gridDim.z;
    int k0 = blockIdx.z * klen;
    float acc[4][4];
#pragma unroll
    for (int i = 0; i < 4; i++)
#pragma unroll
        for (int j = 0; j < 4; j++) acc[i][j] = 0.f;

    int arow = t >> 2, akq = t & 3;
    int bkk = t >> 4, bn4 = t & 15;
    for (int kb = 0; kb < klen; kb += 16) {
        float4 a = *(const float4*)(A + (size_t)(r0 + arow) * K + k0 + kb + akq * 4);
        As[(akq * 4 + 0) * 68 + arow] = a.x;
        As[(akq * 4 + 1) * 68 + arow] = a.y;
        As[(akq * 4 + 2) * 68 + arow] = a.z;
        As[(akq * 4 + 3) * 68 + arow] = a.w;
        *(float4*)(Bs + bkk * 64 + bn4 * 4) =
            *(const float4*)(B + (size_t)(k0 + kb + bkk) * Nn + c0 + bn4 * 4);
        __syncthreads();
#pragma unroll
        for (int kk = 0; kk < 16; kk++) {
            float av[4], bv[4];
            *(float4*)av = *(float4*)(As + kk * 68 + ty * 4);
            *(float4*)bv = *(float4*)(Bs + kk * 64 + tx * 4);
#pragma unroll
            for (int i = 0; i < 4; i++)
#pragma unroll
                for (int j = 0; j < 4; j++) acc[i][j] = fmaf(av[i], bv[j], acc[i][j]);
        }
        __syncthreads();
    }
#pragma unroll
    for (int i = 0; i < 4; i++)
#pragma unroll
        for (int j = 0; j < 4; j++)
            atomicAdd(&Cm[(size_t)(r0 + ty * 4 + i) * Nn + c0 + tx * 4 + j], acc[i][j]);
}

// ---------------- BN over G=256 rows (block per column), in-place ---------
__global__ void k_bnrelu(float* __restrict__ Zm, const float* __restrict__ gg,
                         const float* __restrict__ bb, int Cc, int relu) {
    int c = blockIdx.x, t = threadIdx.x;
    int lane = t & 31, wid = t >> 5;
    __shared__ float a1[8], a2[8];
    float v = Zm[(size_t)t * Cc + c];
    float s1 = v, s2 = v * v;
#pragma unroll
    for (int o = 16; o; o >>= 1) {
        s1 += __shfl_xor_sync(0xffffffffu, s1, o);
        s2 += __shfl_xor_sync(0xffffffffu, s2, o);
    }
    if (lane == 0) { a1[wid] = s1; a2[wid] = s2; }
    __syncthreads();
    if (t == 0) {
        float m = 0.f, q = 0.f;
        for (int i = 0; i < 8; i++) { m += a1[i]; q += a2[i]; }
        m *= (1.f / 256.f);
        q = q * (1.f / 256.f) - m * m;
        a1[0] = m; a2[0] = rsqrtf(q + 1e-5f);
    }
    __syncthreads();
    float o = (v - a1[0]) * a2[0] * gg[c] + bb[c];
    if (relu) o = fmaxf(o, 0.f);
    Zm[(size_t)t * Cc + c] = o;
}

// ---------------- FC3 (256x256x10) fused with final BN --------------------
__global__ void k_fc3bn(const float* __restrict__ w3, const float* __restrict__ g3,
                        const float* __restrict__ be3, float* __restrict__ outp) {
    __shared__ float sc[256 * CLSN];
    __shared__ float mu[CLSN], rs[CLSN];
    int t = threadIdx.x;
    float acc[CLSN];
#pragma unroll
    for (int c = 0; c < CLSN; c++) acc[c] = 0.f;
    for (int k = 0; k < FC2N; k++) {
        float a = g_z2[(size_t)t * FC2N + k];
#pragma unroll
        for (int c = 0; c < CLSN; c++) acc[c] = fmaf(a, w3[k * CLSN + c], acc[c]);
    }
#pragma unroll
    for (int c = 0; c < CLSN; c++) sc[t * CLSN + c] = acc[c];
    __syncthreads();
    if (t < CLSN) {
        float m = 0.f, q = 0.f;
        for (int r = 0; r < 256; r++) {
            float v = sc[r * CLSN + t];
            m += v; q += v * v;
        }
        m *= (1.f / 256.f);
        q = q * (1.f / 256.f) - m * m;
        mu[t] = m;
        rs[t] = rsqrtf(q + 1e-5f) * g3[t];
    }
    __syncthreads();
#pragma unroll
    for (int c = 0; c < CLSN; c++)
        outp[t * CLSN + c] = (sc[t * CLSN + c] - mu[c]) * rs[c] + be3[c];
}

// ---------------- launch ---------------------------------------------------
extern "C" void kernel_launch(void* const* d_in, const int* in_sizes, int n_in,
                              void* d_out, int out_size) {
    const float* x    = (const float*)d_in[0];
    const int*   ei   = (const int*)d_in[3];
    const float* eps  = (const float*)d_in[4];
    const float* w0   = (const float*)d_in[5];
    const float* g0   = (const float*)d_in[7];
    const float* be0  = (const float*)d_in[8];
    const float* w1   = (const float*)d_in[9];
    const float* b1   = (const float*)d_in[10];
    const float* fw1  = (const float*)d_in[11];
    const float* fg1  = (const float*)d_in[13];
    const float* fbe1 = (const float*)d_in[14];
    const float* fw2  = (const float*)d_in[15];
    const float* fg2  = (const float*)d_in[17];
    const float* fbe2 = (const float*)d_in[18];
    const float* fw3  = (const float*)d_in[19];
    const float* fg3  = (const float*)d_in[21];
    const float* fbe3 = (const float*)d_in[22];

    float* hidden = (float*)d_out;
    float* score  = (float*)d_out + (size_t)N_NODES * DD;

    double *X64a, *X64b, *Y64, *T64;
    float *X32a, *X32b, *Y32, *T32, *dz1, *dz2, *dpool;
    cudaGetSymbolAddress((void**)&X64a, g_X64a);
    cudaGetSymbolAddress((void**)&X64b, g_X64b);
    cudaGetSymbolAddress((void**)&Y64, g_Y64);
    cudaGetSymbolAddress((void**)&T64, g_T64);
    cudaGetSymbolAddress((void**)&X32a, g_X32a);
    cudaGetSymbolAddress((void**)&X32b, g_X32b);
    cudaGetSymbolAddress((void**)&Y32, g_Y32);
    cudaGetSymbolAddress((void**)&T32, g_T32);
    cudaGetSymbolAddress((void**)&dz1, g_z1);
    cudaGetSymbolAddress((void**)&dz2, g_z2);
    cudaGetSymbolAddress((void**)&dpool, g_pooled);

    // --- GIN conv (verified R3) ---
    k_init<<<2048, 256>>>(x, eps);
    k_edge<<<(EE * 128) / 256, 256>>>(x, ei);
    k_gemm_nodes<0><<<N_NODES / 128, 256>>>(w0, nullptr, nullptr);
    k_stats<<<N_NODES / 256, 256>>>();
    k_bnfin<<<1, 128>>>(g0, be0);
    k_gemm_nodes<1><<<N_NODES / 128, 256>>>(w1, b1, hidden);

    // --- spectral projector via matrix sign ---
    dim3 tg(2, 2, NG);
    k_gram64<<<tg, 256>>>(hidden);
    k_scale64<<<2048, 256>>>();

    const double QA = 3.4445, QB = -4.7750, QC = 2.0315;
    double* Xc = X64a; double* Xn = X64b;
    for (int it = 0; it < 7; it++) {   // fp64 quintic phase
        k_bgemm<double><<<tg, 256>>>(Xc, Xc, nullptr, Y64, 0.0, 1.0, 0.0);
        k_bgemm<double><<<tg, 256>>>(Y64, Y64, nullptr, T64, 0.0, 1.0, 0.0);
        k_bgemm<double><<<tg, 256>>>(Xc, Y64, T64, Xn, QA, QB, QC);
        double* tmp = Xc; Xc = Xn; Xn = tmp;
    }
    k_cvt<<<2048, 256>>>(Xc);

    float* Xf = X32a; float* Xg2 = X32b;
    for (int it = 0; it < 10; it++) {  // fp32 quintic phase
        k_bgemm<float><<<tg, 256>>>(Xf, Xf, nullptr, Y32, 0.0, 1.0, 0.0);
        k_bgemm<float><<<tg, 256>>>(Y32, Y32, nullptr, T32, 0.0, 1.0, 0.0);
        k_bgemm<float><<<tg, 256>>>(Xf, Y32, T32, Xg2, QA, QB, QC);
        float* tmp = Xf; Xf = Xg2; Xg2 = tmp;
    }
    for (int it = 0; it < 4; it++) {   // cubic NS cleanup
        k_bgemm<float><<<tg, 256>>>(Xf, Xf, nullptr, Y32, 0.0, 1.0, 0.0);
        k_bgemm<float><<<tg, 256>>>(Xf, Y32, nullptr, Xg2, 1.5, -0.5, 0.0);
        float* tmp = Xf; Xf = Xg2; Xg2 = tmp;
    }
    k_pack<<<NG, 256>>>(Xf);

    // --- FC head ---
    k_fc<<<dim3(FC1N / 64, NG / 64, 4), 256>>>(dpool, fw1, dz1, NG, FC1N, TRIU);
    k_bnrelu<<<FC1N, 256>>>(dz1, fg1, fbe1, FC1N, 1);
    k_fc<<<dim3(FC2N / 64, NG / 64, 1), 256>>>(dz1, fw2, dz2, NG, FC2N, FC1N);
    k_bnrelu<<<FC2N, 256>>>(dz2, fg2, fbe2, FC2N, 1);
    k_fc3bn<<<1, 256>>>(fw3, fg3, fbe3, score);
}

// round 6
// speedup vs baseline: 8.4707x; 8.4707x over previous
#include <cuda_runtime.h>
#include <math.h>

#define N_NODES 65536
#define NG      256
#define NPG     256
#define DD      128
#define EE      1048576
#define TRIU    8256
#define FC1N    1024
#define FC2N    256
#define CLSN    10

// ---------------- device scratch (no allocations allowed) ----------------
__device__ float  g_h[N_NODES * DD];
__device__ float  g_y[N_NODES * DD];
__device__ float  g_sum[DD];
__device__ float  g_sumsq[DD];
__device__ float  g_scale[DD];
__device__ float  g_shift[DD];
__device__ double g_B64[NG * DD * DD];   // Gram - I, fp64 (storage only)
__device__ float  g_X32a[NG * DD * DD];
__device__ float  g_X32b[NG * DD * DD];
__device__ float  g_Y32[NG * DD * DD];
__device__ float  g_T32[NG * DD * DD];
__device__ float  g_pooled[NG * TRIU];
__device__ float  g_z1[NG * FC1N];
__device__ float  g_z2[NG * FC2N];

// ---------------- init ----------------------------------------------------
__global__ void k_init(const float* __restrict__ x, const float* __restrict__ eps_p) {
    size_t i = (size_t)blockIdx.x * blockDim.x + threadIdx.x;
    size_t stride = (size_t)gridDim.x * blockDim.x;
    float e = 1.0f + *eps_p;
    for (size_t j = i; j < (size_t)N_NODES * DD; j += stride) g_h[j] = e * x[j];
    for (size_t j = i; j < (size_t)NG * FC1N; j += stride) g_z1[j] = 0.f;
    for (size_t j = i; j < (size_t)NG * FC2N; j += stride) g_z2[j] = 0.f;
    if (i < DD) { g_sum[i] = 0.f; g_sumsq[i] = 0.f; }
}

// ---------------- edge aggregation: atomic scatter-add --------------------
__global__ void k_edge(const float* __restrict__ x, const int* __restrict__ ei) {
    long long tid = (long long)blockIdx.x * 256 + threadIdx.x;
    int f = (int)(tid & 127);
    int e = (int)(tid >> 7);
    int s = ei[e], d = ei[EE + e];
    atomicAdd(&g_h[(size_t)d * DD + f], x[(size_t)s * DD + f]);
}

// ---------------- node GEMMs: 128x128 tile, 256 threads, 8x8/thread ------
template <int MODE>
__global__ void k_gemm_nodes(const float* __restrict__ W,
                             const float* __restrict__ bias,
                             float* __restrict__ outp) {
    __shared__ float As[16 * 132];
    __shared__ float Bs[16 * 128];
    __shared__ float ssc[DD], ssh[DD];
    const float* A = (MODE == 0) ? g_h : g_y;
    float* O = (MODE == 0) ? g_y : outp;
    int t = threadIdx.x;
    if (MODE == 1) {
        if (t < DD) { ssc[t] = g_scale[t]; ssh[t] = g_shift[t]; }
        __syncthreads();
    }
    int tx = t & 15, ty = t >> 4;
    int row0 = blockIdx.x * 128;
    float acc[8][8];
#pragma unroll
    for (int i = 0; i < 8; i++)
#pragma unroll
        for (int j = 0; j < 8; j++) acc[i][j] = 0.f;

    for (int k0 = 0; k0 < DD; k0 += 16) {
#pragma unroll
        for (int ld = 0; ld < 2; ld++) {
            int l = t + ld * 256;
            int row = l >> 2, c4 = l & 3;
            float4 a = *(const float4*)(A + (size_t)(row0 + row) * DD + k0 + c4 * 4);
            if (MODE == 1) {
                int kb = k0 + c4 * 4;
                a.x = fmaxf(fmaf(a.x, ssc[kb + 0], ssh[kb + 0]), 0.f);
                a.y = fmaxf(fmaf(a.y, ssc[kb + 1], ssh[kb + 1]), 0.f);
                a.z = fmaxf(fmaf(a.z, ssc[kb + 2], ssh[kb + 2]), 0.f);
                a.w = fmaxf(fmaf(a.w, ssc[kb + 3], ssh[kb + 3]), 0.f);
            }
            As[(c4 * 4 + 0) * 132 + row] = a.x;
            As[(c4 * 4 + 1) * 132 + row] = a.y;
            As[(c4 * 4 + 2) * 132 + row] = a.z;
            As[(c4 * 4 + 3) * 132 + row] = a.w;
        }
#pragma unroll
        for (int ld = 0; ld < 2; ld++) {
            int l = t + ld * 256;
            int kk = l >> 5, n4 = l & 31;
            *(float4*)(Bs + kk * 128 + n4 * 4) =
                *(const float4*)(W + (size_t)(k0 + kk) * DD + n4 * 4);
        }
        __syncthreads();
#pragma unroll
        for (int kk = 0; kk < 16; kk++) {
            float av[8], bv[8];
            *(float4*)av       = *(float4*)(As + kk * 132 + ty * 8);
            *(float4*)(av + 4) = *(float4*)(As + kk * 132 + ty * 8 + 4);
            *(float4*)bv       = *(float4*)(Bs + kk * 128 + tx * 8);
            *(float4*)(bv + 4) = *(float4*)(Bs + kk * 128 + tx * 8 + 4);
#pragma unroll
            for (int i = 0; i < 8; i++)
#pragma unroll
                for (int j = 0; j < 8; j++) acc[i][j] = fmaf(av[i], bv[j], acc[i][j]);
        }
        __syncthreads();
    }
#pragma unroll
    for (int i = 0; i < 8; i++) {
        int row = row0 + ty * 8 + i;
#pragma unroll
        for (int j4 = 0; j4 < 2; j4++) {
            int c = tx * 8 + j4 * 4;
            float4 o;
            o.x = acc[i][j4 * 4 + 0]; o.y = acc[i][j4 * 4 + 1];
            o.z = acc[i][j4 * 4 + 2]; o.w = acc[i][j4 * 4 + 3];
            if (MODE == 1) {
                o.x += bias[c + 0]; o.y += bias[c + 1];
                o.z += bias[c + 2]; o.w += bias[c + 3];
            }
            *(float4*)(O + (size_t)row * DD + c) = o;
        }
    }
}

// ---------------- BN stats over all nodes ---------------------------------
__global__ void k_stats() {
    __shared__ float sS[256], sQ[256];
    int t = threadIdx.x;
    int col = t & 127, half = t >> 7;
    int r0 = blockIdx.x * 256;
    float s = 0.f, q = 0.f;
    for (int r = r0 + half; r < r0 + 256; r += 2) {
        float v = g_y[(size_t)r * DD + col];
        s += v; q += v * v;
    }
    sS[t] = s; sQ[t] = q;
    __syncthreads();
    if (t < 128) {
        atomicAdd(&g_sum[col], sS[t] + sS[t + 128]);
        atomicAdd(&g_sumsq[col], sQ[t] + sQ[t + 128]);
    }
}

__global__ void k_bnfin(const float* __restrict__ g0, const float* __restrict__ be0) {
    int c = threadIdx.x;
    float m = g_sum[c] * (1.f / (float)N_NODES);
    float var = g_sumsq[c] * (1.f / (float)N_NODES) - m * m;
    float sc = rsqrtf(var + 1e-5f) * g0[c];
    g_scale[c] = sc;
    g_shift[c] = be0[c] - m * sc;
}

// ---------------- Gram: B = Hg^T Hg - I. fp32 chunks, fp64 accumulate ------
__global__ void k_gram(const float* __restrict__ hidden) {
    __shared__ float sA[32 * 65];
    __shared__ float sB[32 * 65];
    int g = blockIdx.z;
    int r0 = blockIdx.y * 64, c0 = blockIdx.x * 64;
    int t = threadIdx.x, tx = t & 15, ty = t >> 4;
    const float* Hg = hidden + (size_t)g * NPG * DD;
    double accd[4][4];
#pragma unroll
    for (int i = 0; i < 4; i++)
#pragma unroll
        for (int j = 0; j < 4; j++) accd[i][j] = 0.0;

    for (int n0 = 0; n0 < NPG; n0 += 32) {
#pragma unroll
        for (int ld = 0; ld < 8; ld++) {
            int l = t + ld * 256;
            int n = l >> 6, cidx = l & 63;
            sA[n * 65 + cidx] = Hg[(size_t)(n0 + n) * DD + r0 + cidx];
            sB[n * 65 + cidx] = Hg[(size_t)(n0 + n) * DD + c0 + cidx];
        }
        __syncthreads();
        float acc[4][4];
#pragma unroll
        for (int i = 0; i < 4; i++)
#pragma unroll
            for (int j = 0; j < 4; j++) acc[i][j] = 0.f;
#pragma unroll 4
        for (int nn = 0; nn < 32; nn++) {
            float av[4], bv[4];
#pragma unroll
            for (int i = 0; i < 4; i++) av[i] = sA[nn * 65 + ty + 16 * i];
#pragma unroll
            for (int j = 0; j < 4; j++) bv[j] = sB[nn * 65 + tx + 16 * j];
#pragma unroll
            for (int i = 0; i < 4; i++)
#pragma unroll
                for (int j = 0; j < 4; j++) acc[i][j] = fmaf(av[i], bv[j], acc[i][j]);
        }
#pragma unroll
        for (int i = 0; i < 4; i++)
#pragma unroll
            for (int j = 0; j < 4; j++) accd[i][j] += (double)acc[i][j];
        __syncthreads();
    }
    double* Bg = g_B64 + (size_t)g * DD * DD;
#pragma unroll
    for (int i = 0; i < 4; i++)
#pragma unroll
        for (int j = 0; j < 4; j++) {
            int gi = r0 + ty + 16 * i, gj = c0 + tx + 16 * j;
            Bg[(size_t)gi * DD + gj] = accd[i][j] - (gi == gj ? 1.0 : 0.0);
        }
}

// ---------------- deflation + normalization -------------------------------
// Spike lambda1 ~ 1700 dominates; deflate to bulk scale (~110) so fp32 sign
// iteration resolves the lambda=1 threshold. Implant +0.5*lam2 on v1 (its
// sign is + since lambda1 >> 1). v1 error couples to near-threshold eigs
// only at 2nd order through the implanted eigenvalue -> fp32 suffices.
__device__ __forceinline__ float redsum128(float x, float* sred, int t) {
    __syncthreads();
    sred[t] = x;
    __syncthreads();
    if (t < 64) sred[t] += sred[t + 64];
    __syncthreads();
    if (t < 32) {
        float v = sred[t] + sred[t + 32];
#pragma unroll
        for (int o = 16; o; o >>= 1) v += __shfl_xor_sync(0xffffffffu, v, o);
        if (t == 0) sred[0] = v;
    }
    __syncthreads();
    return sred[0];
}

__global__ void k_deflate() {
    extern __shared__ float sm[];
    float* Bs   = sm;                 // 128*129
    float* sv   = sm + 128 * 129;     // v1
    float* su   = sv + 128;           // deflated power vec
    float* sred = su + 128;           // 128 reduce
    int g = blockIdx.x, t = threadIdx.x;
    const double* B64 = g_B64 + (size_t)g * DD * DD;

    for (int idx = t; idx < DD * DD; idx += 128)
        Bs[(idx >> 7) * 129 + (idx & 127)] = (float)B64[idx];
    sv[t] = 1.f;
    __syncthreads();

    // power iteration for (lam1, v1)
    float lam1 = 0.f;
    for (int it = 0; it < 14; it++) {
        float w = 0.f;
#pragma unroll 8
        for (int k = 0; k < 128; k++) w = fmaf(Bs[t * 129 + k], sv[k], w);
        lam1 = redsum128(sv[t] * w, sred, t);
        float ww = redsum128(w * w, sred, t);
        float inv = rsqrtf(ww + 1e-30f);
        __syncthreads();
        sv[t] = w * inv;
        __syncthreads();
    }

    // deflated power iteration for lam2 = ||B - lam1 v v^T||_2
    su[t] = __sinf(0.9f * (float)t + 0.5f);
    __syncthreads();
    float lam2 = 0.f;
    for (int it = 0; it < 14; it++) {
        float s = redsum128(sv[t] * su[t], sred, t);
        float w = 0.f;
#pragma unroll 8
        for (int k = 0; k < 128; k++) w = fmaf(Bs[t * 129 + k], su[k], w);
        w -= lam1 * s * sv[t];
        lam2 = fabsf(redsum128(su[t] * w, sred, t));
        float ww = redsum128(w * w, sred, t);
        float inv = rsqrtf(ww + 1e-30f);
        __syncthreads();
        su[t] = w * inv;
        __syncthreads();
    }
    lam2 = fmaxf(lam2, 1e-2f);

    // X0 = (B - (lam1 - 0.5*lam2) v v^T) / (1.10*lam2)   (fp64 arithmetic)
    double dd  = (double)lam1 - 0.5 * (double)lam2;
    double inv = 1.0 / (1.10 * (double)lam2);
    float* X0 = g_X32a + (size_t)g * DD * DD;
    for (int idx = t; idx < DD * DD; idx += 128) {
        int i = idx >> 7, j = idx & 127;
        double val = (B64[idx] - dd * (double)sv[i] * (double)sv[j]) * inv;
        X0[idx] = (float)val;
    }
}

// ---------------- batched GEMM: OUT = A * (alpha*I + beta*B1 + gamma*B2) ---
__global__ void k_bgemm(const float* __restrict__ A, const float* __restrict__ B1,
                        const float* __restrict__ B2, float* __restrict__ OUT,
                        float alpha, float beta, float gamma) {
    __shared__ float As[16 * 65];
    __shared__ float Ms[16 * 64];
    int g = blockIdx.z;
    int r0 = blockIdx.y * 64, c0 = blockIdx.x * 64;
    size_t base = (size_t)g * DD * DD;
    const float* Ag = A + base;
    const float* B1g = B1 + base;
    const float* B2g = B2 ? B2 + base : (const float*)0;
    int t = threadIdx.x, tx = t & 15, ty = t >> 4;
    float acc[4][4];
#pragma unroll
    for (int i = 0; i < 4; i++)
#pragma unroll
        for (int j = 0; j < 4; j++) acc[i][j] = 0.f;

    for (int k0 = 0; k0 < DD; k0 += 16) {
#pragma unroll
        for (int ld = 0; ld < 4; ld++) {
            int l = t + ld * 256;
            int row = l >> 4, kc = l & 15;
            As[kc * 65 + row] = Ag[(size_t)(r0 + row) * DD + k0 + kc];
        }
#pragma unroll
        for (int ld = 0; ld < 4; ld++) {
            int l = t + ld * 256;
            int kr = l >> 6, col = l & 63;
            int gk = k0 + kr, gc = c0 + col;
            float v = beta * B1g[(size_t)gk * DD + gc];
            if (B2g) v += gamma * B2g[(size_t)gk * DD + gc];
            if (gk == gc) v += alpha;
            Ms[kr * 64 + col] = v;
        }
        __syncthreads();
#pragma unroll 4
        for (int kk = 0; kk < 16; kk++) {
            float av[4], mv[4];
#pragma unroll
            for (int i = 0; i < 4; i++) av[i] = As[kk * 65 + ty + 16 * i];
#pragma unroll
            for (int j = 0; j < 4; j++) mv[j] = Ms[kk * 64 + tx + 16 * j];
#pragma unroll
            for (int i = 0; i < 4; i++)
#pragma unroll
                for (int j = 0; j < 4; j++) acc[i][j] = fmaf(av[i], mv[j], acc[i][j]);
        }
        __syncthreads();
    }
    float* Og = OUT + base;
#pragma unroll
    for (int i = 0; i < 4; i++)
#pragma unroll
        for (int j = 0; j < 4; j++)
            Og[(size_t)(r0 + ty + 16 * i) * DD + c0 + tx + 16 * j] = acc[i][j];
}

// ---------------- pack projector P = (I + sign)/2, triu flatten ------------
__global__ void k_pack(const float* __restrict__ X) {
    int g = blockIdx.x, t = threadIdx.x;
    const float* Xg = X + (size_t)g * DD * DD;
    float* Pg = g_pooled + (size_t)g * TRIU;
    for (int idx = t; idx < DD * DD; idx += 256) {
        int i = idx >> 7, j = idx & 127;
        if (j >= i)
            Pg[i * 128 - (i * (i - 1)) / 2 + (j - i)] =
                0.5f * Xg[idx] + (i == j ? 0.5f : 0.f);
    }
}

// ---------------- generic FC GEMM: 64x64 tile, split-K via grid.z ---------
__global__ void k_fc(const float* __restrict__ A, const float* __restrict__ B,
                     float* __restrict__ Cm, int M, int Nn, int K) {
    __shared__ float As[16 * 68];
    __shared__ float Bs[16 * 64];
    int t = threadIdx.x;
    int tx = t & 15, ty = t >> 4;
    int c0 = blockIdx.x * 64, r0 = blockIdx.y * 64;
    int klen = K / gridDim.z;
    int k0 = blockIdx.z * klen;
    float acc[4][4];
#pragma unroll
    for (int i = 0; i < 4; i++)
#pragma unroll
        for (int j = 0; j < 4; j++) acc[i][j] = 0.f;

    int arow = t >> 2, akq = t & 3;
    int bkk = t >> 4, bn4 = t & 15;
    for (int kb = 0; kb < klen; kb += 16) {
        float4 a = *(const float4*)(A + (size_t)(r0 + arow) * K + k0 + kb + akq * 4);
        As[(akq * 4 + 0) * 68 + arow] = a.x;
        As[(akq * 4 + 1) * 68 + arow] = a.y;
        As[(akq * 4 + 2) * 68 + arow] = a.z;
        As[(akq * 4 + 3) * 68 + arow] = a.w;
        *(float4*)(Bs + bkk * 64 + bn4 * 4) =
            *(const float4*)(B + (size_t)(k0 + kb + bkk) * Nn + c0 + bn4 * 4);
        __syncthreads();
#pragma unroll
        for (int kk = 0; kk < 16; kk++) {
            float av[4], bv[4];
            *(float4*)av = *(float4*)(As + kk * 68 + ty * 4);
            *(float4*)bv = *(float4*)(Bs + kk * 64 + tx * 4);
#pragma unroll
            for (int i = 0; i < 4; i++)
#pragma unroll
                for (int j = 0; j < 4; j++) acc[i][j] = fmaf(av[i], bv[j], acc[i][j]);
        }
        __syncthreads();
    }
#pragma unroll
    for (int i = 0; i < 4; i++)
#pragma unroll
        for (int j = 0; j < 4; j++)
            atomicAdd(&Cm[(size_t)(r0 + ty * 4 + i) * Nn + c0 + tx * 4 + j], acc[i][j]);
}

// ---------------- BN over G=256 rows (block per column), in-place ---------
__global__ void k_bnrelu(float* __restrict__ Zm, const float* __restrict__ gg,
                         const float* __restrict__ bb, int Cc, int relu) {
    int c = blockIdx.x, t = threadIdx.x;
    int lane = t & 31, wid = t >> 5;
    __shared__ float a1[8], a2[8];
    float v = Zm[(size_t)t * Cc + c];
    float s1 = v, s2 = v * v;
#pragma unroll
    for (int o = 16; o; o >>= 1) {
        s1 += __shfl_xor_sync(0xffffffffu, s1, o);
        s2 += __shfl_xor_sync(0xffffffffu, s2, o);
    }
    if (lane == 0) { a1[wid] = s1; a2[wid] = s2; }
    __syncthreads();
    if (t == 0) {
        float m = 0.f, q = 0.f;
        for (int i = 0; i < 8; i++) { m += a1[i]; q += a2[i]; }
        m *= (1.f / 256.f);
        q = q * (1.f / 256.f) - m * m;
        a1[0] = m; a2[0] = rsqrtf(q + 1e-5f);
    }
    __syncthreads();
    float o = (v - a1[0]) * a2[0] * gg[c] + bb[c];
    if (relu) o = fmaxf(o, 0.f);
    Zm[(size_t)t * Cc + c] = o;
}

// ---------------- FC3 (256x256x10) fused with final BN --------------------
__global__ void k_fc3bn(const float* __restrict__ w3, const float* __restrict__ g3,
                        const float* __restrict__ be3, float* __restrict__ outp) {
    __shared__ float sc[256 * CLSN];
    __shared__ float mu[CLSN], rs[CLSN];
    int t = threadIdx.x;
    float acc[CLSN];
#pragma unroll
    for (int c = 0; c < CLSN; c++) acc[c] = 0.f;
    for (int k = 0; k < FC2N; k++) {
        float a = g_z2[(size_t)t * FC2N + k];
#pragma unroll
        for (int c = 0; c < CLSN; c++) acc[c] = fmaf(a, w3[k * CLSN + c], acc[c]);
    }
#pragma unroll
    for (int c = 0; c < CLSN; c++) sc[t * CLSN + c] = acc[c];
    __syncthreads();
    if (t < CLSN) {
        float m = 0.f, q = 0.f;
        for (int r = 0; r < 256; r++) {
            float v = sc[r * CLSN + t];
            m += v; q += v * v;
        }
        m *= (1.f / 256.f);
        q = q * (1.f / 256.f) - m * m;
        mu[t] = m;
        rs[t] = rsqrtf(q + 1e-5f) * g3[t];
    }
    __syncthreads();
#pragma unroll
    for (int c = 0; c < CLSN; c++)
        outp[t * CLSN + c] = (sc[t * CLSN + c] - mu[c]) * rs[c] + be3[c];
}

// ---------------- launch ---------------------------------------------------
extern "C" void kernel_launch(void* const* d_in, const int* in_sizes, int n_in,
                              void* d_out, int out_size) {
    const float* x    = (const float*)d_in[0];
    const int*   ei   = (const int*)d_in[3];
    const float* eps  = (const float*)d_in[4];
    const float* w0   = (const float*)d_in[5];
    const float* g0   = (const float*)d_in[7];
    const float* be0  = (const float*)d_in[8];
    const float* w1   = (const float*)d_in[9];
    const float* b1   = (const float*)d_in[10];
    const float* fw1  = (const float*)d_in[11];
    const float* fg1  = (const float*)d_in[13];
    const float* fbe1 = (const float*)d_in[14];
    const float* fw2  = (const float*)d_in[15];
    const float* fg2  = (const float*)d_in[17];
    const float* fbe2 = (const float*)d_in[18];
    const float* fw3  = (const float*)d_in[19];
    const float* fg3  = (const float*)d_in[21];
    const float* fbe3 = (const float*)d_in[22];

    float* hidden = (float*)d_out;
    float* score  = (float*)d_out + (size_t)N_NODES * DD;

    float *X32a, *X32b, *Y32, *T32, *dz1, *dz2, *dpool;
    cudaGetSymbolAddress((void**)&X32a, g_X32a);
    cudaGetSymbolAddress((void**)&X32b, g_X32b);
    cudaGetSymbolAddress((void**)&Y32, g_Y32);
    cudaGetSymbolAddress((void**)&T32, g_T32);
    cudaGetSymbolAddress((void**)&dz1, g_z1);
    cudaGetSymbolAddress((void**)&dz2, g_z2);
    cudaGetSymbolAddress((void**)&dpool, g_pooled);

    const int defl_smem = (128 * 129 + 3 * 128) * (int)sizeof(float);
    cudaFuncSetAttribute(k_deflate, cudaFuncAttributeMaxDynamicSharedMemorySize,
                         defl_smem);

    // --- GIN conv (verified) ---
    k_init<<<2048, 256>>>(x, eps);
    k_edge<<<(EE * 128) / 256, 256>>>(x, ei);
    k_gemm_nodes<0><<<N_NODES / 128, 256>>>(w0, nullptr, nullptr);
    k_stats<<<N_NODES / 256, 256>>>();
    k_bnfin<<<1, 128>>>(g0, be0);
    k_gemm_nodes<1><<<N_NODES / 128, 256>>>(w1, b1, hidden);

    // --- spectral projector: Gram -> deflate -> fp32 sign iteration ---
    dim3 tg(2, 2, NG);
    k_gram<<<tg, 256>>>(hidden);
    k_deflate<<<NG, 128, defl_smem>>>();

    const float QA = 3.4445f, QB = -4.7750f, QC = 2.0315f;
    float* Xc = X32a; float* Xn = X32b;
    for (int it = 0; it < 12; it++) {   // quintic phase
        k_bgemm<<<tg, 256>>>(Xc, Xc, nullptr, Y32, 0.f, 1.f, 0.f);
        k_bgemm<<<tg, 256>>>(Y32, Y32, nullptr, T32, 0.f, 1.f, 0.f);
        k_bgemm<<<tg, 256>>>(Xc, Y32, T32, Xn, QA, QB, QC);
        float* tmp = Xc; Xc = Xn; Xn = tmp;
    }
    for (int it = 0; it < 4; it++) {    // cubic NS cleanup
        k_bgemm<<<tg, 256>>>(Xc, Xc, nullptr, Y32, 0.f, 1.f, 0.f);
        k_bgemm<<<tg, 256>>>(Xc, Y32, nullptr, Xn, 1.5f, -0.5f, 0.f);
        float* tmp = Xc; Xc = Xn; Xn = tmp;
    }
    k_pack<<<NG, 256>>>(Xc);

    // --- FC head ---
    k_fc<<<dim3(FC1N / 64, NG / 64, 4), 256>>>(dpool, fw1, dz1, NG, FC1N, TRIU);
    k_bnrelu<<<FC1N, 256>>>(dz1, fg1, fbe1, FC1N, 1);
    k_fc<<<dim3(FC2N / 64, NG / 64, 1), 256>>>(dz1, fw2, dz2, NG, FC2N, FC1N);
    k_bnrelu<<<FC2N, 256>>>(dz2, fg2, fbe2, FC2N, 1);
    k_fc3bn<<<1, 256>>>(fw3, fg3, fbe3, score);
}

// round 9
// speedup vs baseline: 11.1340x; 1.3144x over previous
#include <cuda_runtime.h>
#include <math.h>

#define N_NODES 65536
#define NG      256
#define NPG     256
#define DD      128
#define EE      1048576
#define TRIU    8256
#define FC1N    1024
#define FC2N    256
#define CLSN    10

// ---------------- device scratch ------------------------------------------
__device__ float  g_h[N_NODES * DD];
__device__ float  g_y[N_NODES * DD];
__device__ float  g_sum[DD];
__device__ float  g_sumsq[DD];
__device__ float  g_scale[DD];
__device__ float  g_shift[DD];
__device__ int    g_deg[N_NODES];
__device__ int    g_off[N_NODES + 1];
__device__ int    g_cur[N_NODES];
__device__ int    g_srcs[EE];
__device__ double g_B64[NG * DD * DD];
__device__ float  g_X32a[NG * DD * DD];
__device__ float  g_X32b[NG * DD * DD];
__device__ float  g_Y32[NG * DD * DD];
__device__ float  g_T32[NG * DD * DD];
__device__ float  g_pooled[NG * TRIU];
__device__ float  g_z1[NG * FC1N];
__device__ float  g_z2[NG * FC2N];

// ---------------- init -----------------------------------------------------
__global__ void k_init() {
    int i = blockIdx.x * blockDim.x + threadIdx.x;
    int stride = gridDim.x * blockDim.x;
    for (int j = i; j < N_NODES; j += stride) { g_deg[j] = 0; g_cur[j] = 0; }
    for (int j = i; j < NG * FC1N; j += stride) g_z1[j] = 0.f;
    for (int j = i; j < NG * FC2N; j += stride) g_z2[j] = 0.f;
    if (i < DD) { g_sum[i] = 0.f; g_sumsq[i] = 0.f; }
}

// ---------------- CSR build ------------------------------------------------
__global__ void k_hist(const int* __restrict__ ei) {
    int e = blockIdx.x * 256 + threadIdx.x;
    atomicAdd(&g_deg[ei[EE + e]], 1);
}

__global__ void k_scan() {  // 1 block, 1024 threads
    __shared__ int wsum[32];
    __shared__ int s_carry;
    int t = threadIdx.x, lane = t & 31, wid = t >> 5;
    if (t == 0) s_carry = 0;
    __syncthreads();
    for (int base = 0; base < N_NODES; base += 1024) {
        int v = g_deg[base + t];
        int x = v;
#pragma unroll
        for (int d = 1; d < 32; d <<= 1) {
            int y = __shfl_up_sync(0xffffffffu, x, d);
            if (lane >= d) x += y;
        }
        if (lane == 31) wsum[wid] = x;
        __syncthreads();
        if (wid == 0) {
            int w = wsum[lane];
#pragma unroll
            for (int d = 1; d < 32; d <<= 1) {
                int y = __shfl_up_sync(0xffffffffu, w, d);
                if (lane >= d) w += y;
            }
            wsum[lane] = w;
        }
        __syncthreads();
        int excl = s_carry + x - v + (wid > 0 ? wsum[wid - 1] : 0);
        g_off[base + t] = excl;
        int btot = wsum[31];
        __syncthreads();
        if (t == 0) s_carry += btot;
        __syncthreads();
        (void)btot;
    }
    if (t == 0) g_off[N_NODES] = s_carry;
}

__global__ void k_scatter(const int* __restrict__ ei) {
    int e = blockIdx.x * 256 + threadIdx.x;
    int d = ei[EE + e];
    int pos = atomicAdd(&g_cur[d], 1);
    g_srcs[g_off[d] + pos] = ei[e];
}

// ---------------- aggregation: one warp per node ---------------------------
__global__ void k_agg(const float* __restrict__ x, const float* __restrict__ eps_p) {
    int warp = (blockIdx.x * blockDim.x + threadIdx.x) >> 5;
    if (warp >= N_NODES) return;
    int lane = threadIdx.x & 31;
    const float4* x4 = (const float4*)x;
    float4 acc = make_float4(0.f, 0.f, 0.f, 0.f);
    int s0 = g_off[warp], s1 = g_off[warp + 1];
    for (int i = s0; i < s1; i++) {
        int s = g_srcs[i];
        float4 v = x4[(size_t)s * 32 + lane];
        acc.x += v.x; acc.y += v.y; acc.z += v.z; acc.w += v.w;
    }
    float e = 1.0f + *eps_p;
    float4 xv = x4[(size_t)warp * 32 + lane];
    acc.x = fmaf(e, xv.x, acc.x);
    acc.y = fmaf(e, xv.y, acc.y);
    acc.z = fmaf(e, xv.z, acc.z);
    acc.w = fmaf(e, xv.w, acc.w);
    ((float4*)g_h)[(size_t)warp * 32 + lane] = acc;
}

// ---------------- node GEMMs: 128x128 tile, 256 threads, 8x8/thread -------
template <int MODE>
__global__ void k_gemm_nodes(const float* __restrict__ W,
                             const float* __restrict__ bias,
                             float* __restrict__ outp) {
    __shared__ float As[16 * 132];
    __shared__ float Bs[16 * 128];
    __shared__ float ssc[DD], ssh[DD];
    const float* A = (MODE == 0) ? g_h : g_y;
    float* O = (MODE == 0) ? g_y : outp;
    int t = threadIdx.x;
    if (MODE == 1) {
        if (t < DD) { ssc[t] = g_scale[t]; ssh[t] = g_shift[t]; }
        __syncthreads();
    }
    int tx = t & 15, ty = t >> 4;
    int row0 = blockIdx.x * 128;
    float acc[8][8];
#pragma unroll
    for (int i = 0; i < 8; i++)
#pragma unroll
        for (int j = 0; j < 8; j++) acc[i][j] = 0.f;

    for (int k0 = 0; k0 < DD; k0 += 16) {
#pragma unroll
        for (int ld = 0; ld < 2; ld++) {
            int l = t + ld * 256;
            int row = l >> 2, c4 = l & 3;
            float4 a = *(const float4*)(A + (size_t)(row0 + row) * DD + k0 + c4 * 4);
            if (MODE == 1) {
                int kb = k0 + c4 * 4;
                a.x = fmaxf(fmaf(a.x, ssc[kb + 0], ssh[kb + 0]), 0.f);
                a.y = fmaxf(fmaf(a.y, ssc[kb + 1], ssh[kb + 1]), 0.f);
                a.z = fmaxf(fmaf(a.z, ssc[kb + 2], ssh[kb + 2]), 0.f);
                a.w = fmaxf(fmaf(a.w, ssc[kb + 3], ssh[kb + 3]), 0.f);
            }
            As[(c4 * 4 + 0) * 132 + row] = a.x;
            As[(c4 * 4 + 1) * 132 + row] = a.y;
            As[(c4 * 4 + 2) * 132 + row] = a.z;
            As[(c4 * 4 + 3) * 132 + row] = a.w;
        }
#pragma unroll
        for (int ld = 0; ld < 2; ld++) {
            int l = t + ld * 256;
            int kk = l >> 5, n4 = l & 31;
            *(float4*)(Bs + kk * 128 + n4 * 4) =
                *(const float4*)(W + (size_t)(k0 + kk) * DD + n4 * 4);
        }
        __syncthreads();
#pragma unroll
        for (int kk = 0; kk < 16; kk++) {
            float av[8], bv[8];
            *(float4*)av       = *(float4*)(As + kk * 132 + ty * 8);
            *(float4*)(av + 4) = *(float4*)(As + kk * 132 + ty * 8 + 4);
            *(float4*)bv       = *(float4*)(Bs + kk * 128 + tx * 8);
            *(float4*)(bv + 4) = *(float4*)(Bs + kk * 128 + tx * 8 + 4);
#pragma unroll
            for (int i = 0; i < 8; i++)
#pragma unroll
                for (int j = 0; j < 8; j++) acc[i][j] = fmaf(av[i], bv[j], acc[i][j]);
        }
        __syncthreads();
    }
#pragma unroll
    for (int i = 0; i < 8; i++) {
        int row = row0 + ty * 8 + i;
#pragma unroll
        for (int j4 = 0; j4 < 2; j4++) {
            int c = tx * 8 + j4 * 4;
            float4 o;
            o.x = acc[i][j4 * 4 + 0]; o.y = acc[i][j4 * 4 + 1];
            o.z = acc[i][j4 * 4 + 2]; o.w = acc[i][j4 * 4 + 3];
            if (MODE == 1) {
                o.x += bias[c + 0]; o.y += bias[c + 1];
                o.z += bias[c + 2]; o.w += bias[c + 3];
            }
            *(float4*)(O + (size_t)row * DD + c) = o;
        }
    }
}

// ---------------- BN stats over all nodes ----------------------------------
__global__ void k_stats() {
    __shared__ float sS[256], sQ[256];
    int t = threadIdx.x;
    int col = t & 127, half = t >> 7;
    int r0 = blockIdx.x * 256;
    float s = 0.f, q = 0.f;
    for (int r = r0 + half; r < r0 + 256; r += 2) {
        float v = g_y[(size_t)r * DD + col];
        s += v; q += v * v;
    }
    sS[t] = s; sQ[t] = q;
    __syncthreads();
    if (t < 128) {
        atomicAdd(&g_sum[col], sS[t] + sS[t + 128]);
        atomicAdd(&g_sumsq[col], sQ[t] + sQ[t + 128]);
    }
}

__global__ void k_bnfin(const float* __restrict__ g0, const float* __restrict__ be0) {
    int c = threadIdx.x;
    float m = g_sum[c] * (1.f / (float)N_NODES);
    float var = g_sumsq[c] * (1.f / (float)N_NODES) - m * m;
    float sc = rsqrtf(var + 1e-5f) * g0[c];
    g_scale[c] = sc;
    g_shift[c] = be0[c] - m * sc;
}

// ---------------- Gram: B = Hg^T Hg - I (fp32 chunks, fp64 accumulate) -----
__global__ void k_gram(const float* __restrict__ hidden) {
    __shared__ float sA[32 * 65];
    __shared__ float sB[32 * 65];
    int g = blockIdx.z;
    int r0 = blockIdx.y * 64, c0 = blockIdx.x * 64;
    int t = threadIdx.x, tx = t & 15, ty = t >> 4;
    const float* Hg = hidden + (size_t)g * NPG * DD;
    double accd[4][4];
#pragma unroll
    for (int i = 0; i < 4; i++)
#pragma unroll
        for (int j = 0; j < 4; j++) accd[i][j] = 0.0;

    for (int n0 = 0; n0 < NPG; n0 += 32) {
#pragma unroll
        for (int ld = 0; ld < 8; ld++) {
            int l = t + ld * 256;
            int n = l >> 6, cidx = l & 63;
            sA[n * 65 + cidx] = Hg[(size_t)(n0 + n) * DD + r0 + cidx];
            sB[n * 65 + cidx] = Hg[(size_t)(n0 + n) * DD + c0 + cidx];
        }
        __syncthreads();
        float acc[4][4];
#pragma unroll
        for (int i = 0; i < 4; i++)
#pragma unroll
            for (int j = 0; j < 4; j++) acc[i][j] = 0.f;
#pragma unroll 4
        for (int nn = 0; nn < 32; nn++) {
            float av[4], bv[4];
#pragma unroll
            for (int i = 0; i < 4; i++) av[i] = sA[nn * 65 + ty + 16 * i];
#pragma unroll
            for (int j = 0; j < 4; j++) bv[j] = sB[nn * 65 + tx + 16 * j];
#pragma unroll
            for (int i = 0; i < 4; i++)
#pragma unroll
                for (int j = 0; j < 4; j++) acc[i][j] = fmaf(av[i], bv[j], acc[i][j]);
        }
#pragma unroll
        for (int i = 0; i < 4; i++)
#pragma unroll
            for (int j = 0; j < 4; j++) accd[i][j] += (double)acc[i][j];
        __syncthreads();
    }
    double* Bg = g_B64 + (size_t)g * DD * DD;
#pragma unroll
    for (int i = 0; i < 4; i++)
#pragma unroll
        for (int j = 0; j < 4; j++) {
            int gi = r0 + ty + 16 * i, gj = c0 + tx + 16 * j;
            Bg[(size_t)gi * DD + gj] = accd[i][j] - (gi == gj ? 1.0 : 0.0);
        }
}

// ---------------- deflation + normalization --------------------------------
__device__ __forceinline__ float redsum128(float x, float* sred, int t) {
    __syncthreads();
    sred[t] = x;
    __syncthreads();
    if (t < 64) sred[t] += sred[t + 64];
    __syncthreads();
    if (t < 32) {
        float v = sred[t] + sred[t + 32];
#pragma unroll
        for (int o = 16; o; o >>= 1) v += __shfl_xor_sync(0xffffffffu, v, o);
        if (t == 0) sred[0] = v;
    }
    __syncthreads();
    return sred[0];
}

__global__ void k_deflate() {
    extern __shared__ float sm[];
    float* Bs   = sm;               // 128*129
    float* sv   = sm + 128 * 129;
    float* su   = sv + 128;
    float* sred = su + 128;
    int g = blockIdx.x, t = threadIdx.x;
    const double* B64 = g_B64 + (size_t)g * DD * DD;

    for (int idx = t; idx < DD * DD; idx += 128)
        Bs[(idx >> 7) * 129 + (idx & 127)] = (float)B64[idx];
    sv[t] = 1.f;
    __syncthreads();

    float lam1 = 0.f;
    for (int it = 0; it < 14; it++) {
        float w = 0.f;
#pragma unroll 8
        for (int k = 0; k < 128; k++) w = fmaf(Bs[t * 129 + k], sv[k], w);
        lam1 = redsum128(sv[t] * w, sred, t);
        float ww = redsum128(w * w, sred, t);
        float inv = rsqrtf(ww + 1e-30f);
        __syncthreads();
        sv[t] = w * inv;
        __syncthreads();
    }

    su[t] = __sinf(0.9f * (float)t + 0.5f);
    __syncthreads();
    float lam2 = 0.f;
    for (int it = 0; it < 14; it++) {
        float s = redsum128(sv[t] * su[t], sred, t);
        float w = 0.f;
#pragma unroll 8
        for (int k = 0; k < 128; k++) w = fmaf(Bs[t * 129 + k], su[k], w);
        w -= lam1 * s * sv[t];
        lam2 = fabsf(redsum128(su[t] * w, sred, t));
        float ww = redsum128(w * w, sred, t);
        float inv = rsqrtf(ww + 1e-30f);
        __syncthreads();
        su[t] = w * inv;
        __syncthreads();
    }
    lam2 = fmaxf(lam2, 1e-2f);

    double dd  = (double)lam1 - 0.5 * (double)lam2;
    double inv = 1.0 / (1.10 * (double)lam2);
    float* X0 = g_X32a + (size_t)g * DD * DD;
    for (int idx = t; idx < DD * DD; idx += 128) {
        int i = idx >> 7, j = idx & 127;
        X0[idx] = (float)((B64[idx] - dd * (double)sv[i] * (double)sv[j]) * inv);
    }
}

// ---------------- batched GEMM 128x128: OUT = A*(aI + b*B1 + c*B2) ---------
__global__ void k_bgemm(const float* __restrict__ A, const float* __restrict__ B1,
                        const float* __restrict__ B2, float* __restrict__ OUT,
                        float alpha, float beta, float gamma) {
    __shared__ float As[16 * 132];
    __shared__ float Ms[16 * 128];
    int g = blockIdx.x;
    size_t base = (size_t)g * DD * DD;
    const float* Ag = A + base;
    const float* B1g = B1 + base;
    const float* B2g = B2 ? B2 + base : (const float*)0;
    int t = threadIdx.x, tx = t & 15, ty = t >> 4;
    float acc[8][8];
#pragma unroll
    for (int i = 0; i < 8; i++)
#pragma unroll
        for (int j = 0; j < 8; j++) acc[i][j] = 0.f;

    for (int k0 = 0; k0 < DD; k0 += 16) {
#pragma unroll
        for (int ld = 0; ld < 2; ld++) {
            int l = t + ld * 256;
            int row = l >> 2, c4 = l & 3;
            float4 a = *(const float4*)(Ag + (size_t)row * DD + k0 + c4 * 4);
            As[(c4 * 4 + 0) * 132 + row] = a.x;
            As[(c4 * 4 + 1) * 132 + row] = a.y;
            As[(c4 * 4 + 2) * 132 + row] = a.z;
            As[(c4 * 4 + 3) * 132 + row] = a.w;
        }
#pragma unroll
        for (int ld = 0; ld < 2; ld++) {
            int l = t + ld * 256;
            int kr = l >> 5, n4 = l & 31;
            int gk = k0 + kr;
            float4 v = *(const float4*)(B1g + (size_t)gk * DD + n4 * 4);
            v.x *= beta; v.y *= beta; v.z *= beta; v.w *= beta;
            if (B2g) {
                float4 w = *(const float4*)(B2g + (size_t)gk * DD + n4 * 4);
                v.x = fmaf(gamma, w.x, v.x); v.y = fmaf(gamma, w.y, v.y);
                v.z = fmaf(gamma, w.z, v.z); v.w = fmaf(gamma, w.w, v.w);
            }
            int dcol = gk - n4 * 4;
            if (dcol >= 0 && dcol < 4) ((float*)&v)[dcol] += alpha;
            *(float4*)(Ms + kr * 128 + n4 * 4) = v;
        }
        __syncthreads();
#pragma unroll
        for (int kk = 0; kk < 16; kk++) {
            float av[8], bv[8];
            *(float4*)av       = *(float4*)(As + kk * 132 + ty * 8);
            *(float4*)(av + 4) = *(float4*)(As + kk * 132 + ty * 8 + 4);
            *(float4*)bv       = *(float4*)(Ms + kk * 128 + tx * 8);
            *(float4*)(bv + 4) = *(float4*)(Ms + kk * 128 + tx * 8 + 4);
#pragma unroll
            for (int i = 0; i < 8; i++)
#pragma unroll
                for (int j = 0; j < 8; j++) acc[i][j] = fmaf(av[i], bv[j], acc[i][j]);
        }
        __syncthreads();
    }
    float* Og = OUT + base;
#pragma unroll
    for (int i = 0; i < 8; i++) {
        int row = ty * 8 + i;
#pragma unroll
        for (int j4 = 0; j4 < 2; j4++) {
            float4 o;
            o.x = acc[i][j4 * 4 + 0]; o.y = acc[i][j4 * 4 + 1];
            o.z = acc[i][j4 * 4 + 2]; o.w = acc[i][j4 * 4 + 3];
            *(float4*)(Og + (size_t)row * DD + tx * 8 + j4 * 4) = o;
        }
    }
}

// ---------------- pack projector -------------------------------------------
__global__ void k_pack(const float* __restrict__ X) {
    int g = blockIdx.x, t = threadIdx.x;
    const float* Xg = X + (size_t)g * DD * DD;
    float* Pg = g_pooled + (size_t)g * TRIU;
    for (int idx = t; idx < DD * DD; idx += 256) {
        int i = idx >> 7, j = idx & 127;
        if (j >= i)
            Pg[i * 128 - (i * (i - 1)) / 2 + (j - i)] =
                0.5f * Xg[idx] + (i == j ? 0.5f : 0.f);
    }
}

// ---------------- generic FC GEMM: 64x64 tile, split-K via grid.z ----------
__global__ void k_fc(const float* __restrict__ A, const float* __restrict__ B,
                     float* __restrict__ Cm, int M, int Nn, int K) {
    __shared__ float As[16 * 68];
    __shared__ float Bs[16 * 64];
    int t = threadIdx.x;
    int tx = t & 15, ty = t >> 4;
    int c0 = blockIdx.x * 64, r0 = blockIdx.y * 64;
    int klen = K / gridDim.z;
    int k0 = blockIdx.z * klen;
    float acc[4][4];
#pragma unroll
    for (int i = 0; i < 4; i++)
#pragma unroll
        for (int j = 0; j < 4; j++) acc[i][j] = 0.f;

    int arow = t >> 2, akq = t & 3;
    int bkk = t >> 4, bn4 = t & 15;
    for (int kb = 0; kb < klen; kb += 16) {
        float4 a = *(const float4*)(A + (size_t)(r0 + arow) * K + k0 + kb + akq * 4);
        As[(akq * 4 + 0) * 68 + arow] = a.x;
        As[(akq * 4 + 1) * 68 + arow] = a.y;
        As[(akq * 4 + 2) * 68 + arow] = a.z;
        As[(akq * 4 + 3) * 68 + arow] = a.w;
        *(float4*)(Bs + bkk * 64 + bn4 * 4) =
            *(const float4*)(B + (size_t)(k0 + kb + bkk) * Nn + c0 + bn4 * 4);
        __syncthreads();
#pragma unroll
        for (int kk = 0; kk < 16; kk++) {
            float av[4], bv[4];
            *(float4*)av = *(float4*)(As + kk * 68 + ty * 4);
            *(float4*)bv = *(float4*)(Bs + kk * 64 + tx * 4);
#pragma unroll
            for (int i = 0; i < 4; i++)
#pragma unroll
                for (int j = 0; j < 4; j++) acc[i][j] = fmaf(av[i], bv[j], acc[i][j]);
        }
        __syncthreads();
    }
#pragma unroll
    for (int i = 0; i < 4; i++)
#pragma unroll
        for (int j = 0; j < 4; j++)
            atomicAdd(&Cm[(size_t)(r0 + ty * 4 + i) * Nn + c0 + tx * 4 + j], acc[i][j]);
}

// ---------------- BN over G=256 rows ---------------------------------------
__global__ void k_bnrelu(float* __restrict__ Zm, const float* __restrict__ gg,
                         const float* __restrict__ bb, int Cc, int relu) {
    int c = blockIdx.x, t = threadIdx.x;
    int lane = t & 31, wid = t >> 5;
    __shared__ float a1[8], a2[8];
    float v = Zm[(size_t)t * Cc + c];
    float s1 = v, s2 = v * v;
#pragma unroll
    for (int o = 16; o; o >>= 1) {
        s1 += __shfl_xor_sync(0xffffffffu, s1, o);
        s2 += __shfl_xor_sync(0xffffffffu, s2, o);
    }
    if (lane == 0) { a1[wid] = s1; a2[wid] = s2; }
    __syncthreads();
    if (t == 0) {
        float m = 0.f, q = 0.f;
        for (int i = 0; i < 8; i++) { m += a1[i]; q += a2[i]; }
        m *= (1.f / 256.f);
        q = q * (1.f / 256.f) - m * m;
        a1[0] = m; a2[0] = rsqrtf(q + 1e-5f);
    }
    __syncthreads();
    float o = (v - a1[0]) * a2[0] * gg[c] + bb[c];
    if (relu) o = fmaxf(o, 0.f);
    Zm[(size_t)t * Cc + c] = o;
}

// ---------------- FC3 fused with final BN ----------------------------------
__global__ void k_fc3bn(const float* __restrict__ w3, const float* __restrict__ g3,
                        const float* __restrict__ be3, float* __restrict__ outp) {
    __shared__ float sc[256 * CLSN];
    __shared__ float mu[CLSN], rs[CLSN];
    int t = threadIdx.x;
    float acc[CLSN];
#pragma unroll
    for (int c = 0; c < CLSN; c++) acc[c] = 0.f;
    for (int k = 0; k < FC2N; k++) {
        float a = g_z2[(size_t)t * FC2N + k];
#pragma unroll
        for (int c = 0; c < CLSN; c++) acc[c] = fmaf(a, w3[k * CLSN + c], acc[c]);
    }
#pragma unroll
    for (int c = 0; c < CLSN; c++) sc[t * CLSN + c] = acc[c];
    __syncthreads();
    if (t < CLSN) {
        float m = 0.f, q = 0.f;
        for (int r = 0; r < 256; r++) {
            float v = sc[r * CLSN + t];
            m += v; q += v * v;
        }
        m *= (1.f / 256.f);
        q = q * (1.f / 256.f) - m * m;
        mu[t] = m;
        rs[t] = rsqrtf(q + 1e-5f) * g3[t];
    }
    __syncthreads();
#pragma unroll
    for (int c = 0; c < CLSN; c++)
        outp[t * CLSN + c] = (sc[t * CLSN + c] - mu[c]) * rs[c] + be3[c];
}

// ---------------- launch ----------------------------------------------------
extern "C" void kernel_launch(void* const* d_in, const int* in_sizes, int n_in,
                              void* d_out, int out_size) {
    const float* x    = (const float*)d_in[0];
    const int*   ei   = (const int*)d_in[3];
    const float* eps  = (const float*)d_in[4];
    const float* w0   = (const float*)d_in[5];
    const float* g0   = (const float*)d_in[7];
    const float* be0  = (const float*)d_in[8];
    const float* w1   = (const float*)d_in[9];
    const float* b1   = (const float*)d_in[10];
    const float* fw1  = (const float*)d_in[11];
    const float* fg1  = (const float*)d_in[13];
    const float* fbe1 = (const float*)d_in[14];
    const float* fw2  = (const float*)d_in[15];
    const float* fg2  = (const float*)d_in[17];
    const float* fbe2 = (const float*)d_in[18];
    const float* fw3  = (const float*)d_in[19];
    const float* fg3  = (const float*)d_in[21];
    const float* fbe3 = (const float*)d_in[22];

    float* hidden = (float*)d_out;
    float* score  = (float*)d_out + (size_t)N_NODES * DD;

    float *X32a, *X32b, *Y32, *T32, *dz1, *dz2, *dpool;
    cudaGetSymbolAddress((void**)&X32a, g_X32a);
    cudaGetSymbolAddress((void**)&X32b, g_X32b);
    cudaGetSymbolAddress((void**)&Y32, g_Y32);
    cudaGetSymbolAddress((void**)&T32, g_T32);
    cudaGetSymbolAddress((void**)&dz1, g_z1);
    cudaGetSymbolAddress((void**)&dz2, g_z2);
    cudaGetSymbolAddress((void**)&dpool, g_pooled);

    const int defl_smem = (128 * 129 + 3 * 128) * (int)sizeof(float);
    cudaFuncSetAttribute(k_deflate, cudaFuncAttributeMaxDynamicSharedMemorySize,
                         defl_smem);

    // --- GIN conv: CSR build + gather, GEMMs, BN ---
    k_init<<<512, 256>>>();
    k_hist<<<EE / 256, 256>>>(ei);
    k_scan<<<1, 1024>>>();
    k_scatter<<<EE / 256, 256>>>(ei);
    k_agg<<<N_NODES * 32 / 256, 256>>>(x, eps);
    k_gemm_nodes<0><<<N_NODES / 128, 256>>>(w0, nullptr, nullptr);
    k_stats<<<N_NODES / 256, 256>>>();
    k_bnfin<<<1, 128>>>(g0, be0);
    k_gemm_nodes<1><<<N_NODES / 128, 256>>>(w1, b1, hidden);

    // --- spectral projector: Gram -> deflate -> fp32 sign iteration ---
    k_gram<<<dim3(2, 2, NG), 256>>>(hidden);
    k_deflate<<<NG, 128, defl_smem>>>();

    // Schedule restored to the R5-proven 12 quintic + 4 cubic (R6's 8+4 left
    // boundary eigenvalues at ~0.73 instead of 1 -> 5.4e-2 error).
    const float QA = 3.4445f, QB = -4.7750f, QC = 2.0315f;
    float* Xc = X32a; float* Xn = X32b;
    for (int it = 0; it < 12; it++) {   // quintic phase
        k_bgemm<<<NG, 256>>>(Xc, Xc, nullptr, Y32, 0.f, 1.f, 0.f);
        k_bgemm<<<NG, 256>>>(Y32, Y32, nullptr, T32, 0.f, 1.f, 0.f);
        k_bgemm<<<NG, 256>>>(Xc, Y32, T32, Xn, QA, QB, QC);
        float* tmp = Xc; Xc = Xn; Xn = tmp;
    }
    for (int it = 0; it < 4; it++) {    // cubic NS cleanup
        k_bgemm<<<NG, 256>>>(Xc, Xc, nullptr, Y32, 0.f, 1.f, 0.f);
        k_bgemm<<<NG, 256>>>(Xc, Y32, nullptr, Xn, 1.5f, -0.5f, 0.f);
        float* tmp = Xc; Xc = Xn; Xn = tmp;
    }
    k_pack<<<NG, 256>>>(Xc);

    // --- FC head ---
    k_fc<<<dim3(FC1N / 64, NG / 64, 12), 256>>>(dpool, fw1, dz1, NG, FC1N, TRIU);
    k_bnrelu<<<FC1N, 256>>>(dz1, fg1, fbe1, FC1N, 1);
    k_fc<<<dim3(FC2N / 64, NG / 64, 1), 256>>>(dz1, fw2, dz2, NG, FC2N, FC1N);
    k_bnrelu<<<FC2N, 256>>>(dz2, fg2, fbe2, FC2N, 1);
    k_fc3bn<<<1, 256>>>(fw3, fg3, fbe3, score);
}

// round 11
// speedup vs baseline: 13.1489x; 1.1810x over previous
#include <cuda_runtime.h>
#include <math.h>

#define N_NODES 65536
#define NG      256
#define NPG     256
#define DD      128
#define EE      1048576
#define TRIU    8256
#define FC1N    1024
#define FC2N    256
#define CLSN    10

// ---------------- device scratch ------------------------------------------
__device__ float  g_h[N_NODES * DD];
__device__ float  g_y[N_NODES * DD];
__device__ float  g_sum[DD];
__device__ float  g_sumsq[DD];
__device__ float  g_scale[DD];
__device__ float  g_shift[DD];
__device__ int    g_deg[N_NODES];
__device__ int    g_off[N_NODES + 1];
__device__ int    g_cur[N_NODES];
__device__ int    g_srcs[EE];
__device__ double g_B64[NG * DD * DD];
__device__ float  g_X32a[NG * DD * DD];
__device__ float  g_X32b[NG * DD * DD];
__device__ float  g_Y32[NG * DD * DD];
__device__ float  g_T32[NG * DD * DD];
__device__ float  g_pooled[NG * TRIU];
__device__ float  g_z1[NG * FC1N];
__device__ float  g_z2[NG * FC2N];

// ---------------- init -----------------------------------------------------
__global__ void k_init() {
    int i = blockIdx.x * blockDim.x + threadIdx.x;
    int stride = gridDim.x * blockDim.x;
    for (int j = i; j < N_NODES; j += stride) { g_deg[j] = 0; g_cur[j] = 0; }
    for (int j = i; j < NG * FC1N; j += stride) g_z1[j] = 0.f;
    for (int j = i; j < NG * FC2N; j += stride) g_z2[j] = 0.f;
    if (i < DD) { g_sum[i] = 0.f; g_sumsq[i] = 0.f; }
}

// ---------------- CSR build ------------------------------------------------
__global__ void k_hist(const int* __restrict__ ei) {
    int e = blockIdx.x * 256 + threadIdx.x;
    atomicAdd(&g_deg[ei[EE + e]], 1);
}

__global__ void k_scan() {  // 1 block, 1024 threads
    __shared__ int wsum[32];
    __shared__ int s_carry;
    int t = threadIdx.x, lane = t & 31, wid = t >> 5;
    if (t == 0) s_carry = 0;
    __syncthreads();
    for (int base = 0; base < N_NODES; base += 1024) {
        int v = g_deg[base + t];
        int x = v;
#pragma unroll
        for (int d = 1; d < 32; d <<= 1) {
            int y = __shfl_up_sync(0xffffffffu, x, d);
            if (lane >= d) x += y;
        }
        if (lane == 31) wsum[wid] = x;
        __syncthreads();
        if (wid == 0) {
            int w = wsum[lane];
#pragma unroll
            for (int d = 1; d < 32; d <<= 1) {
                int y = __shfl_up_sync(0xffffffffu, w, d);
                if (lane >= d) w += y;
            }
            wsum[lane] = w;
        }
        __syncthreads();
        int excl = s_carry + x - v + (wid > 0 ? wsum[wid - 1] : 0);
        g_off[base + t] = excl;
        int btot = wsum[31];
        __syncthreads();
        if (t == 0) s_carry += btot;
        __syncthreads();
        (void)btot;
    }
    if (t == 0) g_off[N_NODES] = s_carry;
}

__global__ void k_scatter(const int* __restrict__ ei) {
    int e = blockIdx.x * 256 + threadIdx.x;
    int d = ei[EE + e];
    int pos = atomicAdd(&g_cur[d], 1);
    g_srcs[g_off[d] + pos] = ei[e];
}

// ---------------- aggregation: one warp per node ---------------------------
__global__ void k_agg(const float* __restrict__ x, const float* __restrict__ eps_p) {
    int warp = (blockIdx.x * blockDim.x + threadIdx.x) >> 5;
    if (warp >= N_NODES) return;
    int lane = threadIdx.x & 31;
    const float4* x4 = (const float4*)x;
    float4 acc = make_float4(0.f, 0.f, 0.f, 0.f);
    int s0 = g_off[warp], s1 = g_off[warp + 1];
    for (int i = s0; i < s1; i++) {
        int s = g_srcs[i];
        float4 v = x4[(size_t)s * 32 + lane];
        acc.x += v.x; acc.y += v.y; acc.z += v.z; acc.w += v.w;
    }
    float e = 1.0f + *eps_p;
    float4 xv = x4[(size_t)warp * 32 + lane];
    acc.x = fmaf(e, xv.x, acc.x);
    acc.y = fmaf(e, xv.y, acc.y);
    acc.z = fmaf(e, xv.z, acc.z);
    acc.w = fmaf(e, xv.w, acc.w);
    ((float4*)g_h)[(size_t)warp * 32 + lane] = acc;
}

// ---------------- node GEMMs: 128x128 tile, 256 threads, 8x8/thread -------
template <int MODE>
__global__ void k_gemm_nodes(const float* __restrict__ W,
                             const float* __restrict__ bias,
                             float* __restrict__ outp) {
    __shared__ float As[16 * 132];
    __shared__ float Bs[16 * 128];
    __shared__ float ssc[DD], ssh[DD];
    const float* A = (MODE == 0) ? g_h : g_y;
    float* O = (MODE == 0) ? g_y : outp;
    int t = threadIdx.x;
    if (MODE == 1) {
        if (t < DD) { ssc[t] = g_scale[t]; ssh[t] = g_shift[t]; }
        __syncthreads();
    }
    int tx = t & 15, ty = t >> 4;
    int row0 = blockIdx.x * 128;
    float acc[8][8];
#pragma unroll
    for (int i = 0; i < 8; i++)
#pragma unroll
        for (int j = 0; j < 8; j++) acc[i][j] = 0.f;

    for (int k0 = 0; k0 < DD; k0 += 16) {
#pragma unroll
        for (int ld = 0; ld < 2; ld++) {
            int l = t + ld * 256;
            int row = l >> 2, c4 = l & 3;
            float4 a = *(const float4*)(A + (size_t)(row0 + row) * DD + k0 + c4 * 4);
            if (MODE == 1) {
                int kb = k0 + c4 * 4;
                a.x = fmaxf(fmaf(a.x, ssc[kb + 0], ssh[kb + 0]), 0.f);
                a.y = fmaxf(fmaf(a.y, ssc[kb + 1], ssh[kb + 1]), 0.f);
                a.z = fmaxf(fmaf(a.z, ssc[kb + 2], ssh[kb + 2]), 0.f);
                a.w = fmaxf(fmaf(a.w, ssc[kb + 3], ssh[kb + 3]), 0.f);
            }
            As[(c4 * 4 + 0) * 132 + row] = a.x;
            As[(c4 * 4 + 1) * 132 + row] = a.y;
            As[(c4 * 4 + 2) * 132 + row] = a.z;
            As[(c4 * 4 + 3) * 132 + row] = a.w;
        }
#pragma unroll
        for (int ld = 0; ld < 2; ld++) {
            int l = t + ld * 256;
            int kk = l >> 5, n4 = l & 31;
            *(float4*)(Bs + kk * 128 + n4 * 4) =
                *(const float4*)(W + (size_t)(k0 + kk) * DD + n4 * 4);
        }
        __syncthreads();
#pragma unroll
        for (int kk = 0; kk < 16; kk++) {
            float av[8], bv[8];
            *(float4*)av       = *(float4*)(As + kk * 132 + ty * 8);
            *(float4*)(av + 4) = *(float4*)(As + kk * 132 + ty * 8 + 4);
            *(float4*)bv       = *(float4*)(Bs + kk * 128 + tx * 8);
            *(float4*)(bv + 4) = *(float4*)(Bs + kk * 128 + tx * 8 + 4);
#pragma unroll
            for (int i = 0; i < 8; i++)
#pragma unroll
                for (int j = 0; j < 8; j++) acc[i][j] = fmaf(av[i], bv[j], acc[i][j]);
        }
        __syncthreads();
    }
#pragma unroll
    for (int i = 0; i < 8; i++) {
        int row = row0 + ty * 8 + i;
#pragma unroll
        for (int j4 = 0; j4 < 2; j4++) {
            int c = tx * 8 + j4 * 4;
            float4 o;
            o.x = acc[i][j4 * 4 + 0]; o.y = acc[i][j4 * 4 + 1];
            o.z = acc[i][j4 * 4 + 2]; o.w = acc[i][j4 * 4 + 3];
            if (MODE == 1) {
                o.x += bias[c + 0]; o.y += bias[c + 1];
                o.z += bias[c + 2]; o.w += bias[c + 3];
            }
            *(float4*)(O + (size_t)row * DD + c) = o;
        }
    }
}

// ---------------- BN stats over all nodes ----------------------------------
__global__ void k_stats() {
    __shared__ float sS[256], sQ[256];
    int t = threadIdx.x;
    int col = t & 127, half = t >> 7;
    int r0 = blockIdx.x * 256;
    float s = 0.f, q = 0.f;
    for (int r = r0 + half; r < r0 + 256; r += 2) {
        float v = g_y[(size_t)r * DD + col];
        s += v; q += v * v;
    }
    sS[t] = s; sQ[t] = q;
    __syncthreads();
    if (t < 128) {
        atomicAdd(&g_sum[col], sS[t] + sS[t + 128]);
        atomicAdd(&g_sumsq[col], sQ[t] + sQ[t + 128]);
    }
}

__global__ void k_bnfin(const float* __restrict__ g0, const float* __restrict__ be0) {
    int c = threadIdx.x;
    float m = g_sum[c] * (1.f / (float)N_NODES);
    float var = g_sumsq[c] * (1.f / (float)N_NODES) - m * m;
    float sc = rsqrtf(var + 1e-5f) * g0[c];
    g_scale[c] = sc;
    g_shift[c] = be0[c] - m * sc;
}

// ---------------- Gram (symmetric 3-tile): B = Hg^T Hg - I -----------------
// blockIdx.x: 0->(0,0) 1->(0,64) 2->(64,64); tile 1 mirrors to (64,0).
__global__ void k_gram(const float* __restrict__ hidden) {
    __shared__ float sA[32 * 65];
    __shared__ float sB[32 * 65];
    int g = blockIdx.y;
    int tile = blockIdx.x;
    int r0 = (tile == 2) ? 64 : 0;
    int c0 = (tile == 0) ? 0 : 64;
    int t = threadIdx.x, tx = t & 15, ty = t >> 4;
    const float* Hg = hidden + (size_t)g * NPG * DD;
    double accd[4][4];
#pragma unroll
    for (int i = 0; i < 4; i++)
#pragma unroll
        for (int j = 0; j < 4; j++) accd[i][j] = 0.0;

    for (int n0 = 0; n0 < NPG; n0 += 32) {
#pragma unroll
        for (int ld = 0; ld < 8; ld++) {
            int l = t + ld * 256;
            int n = l >> 6, cidx = l & 63;
            sA[n * 65 + cidx] = Hg[(size_t)(n0 + n) * DD + r0 + cidx];
            sB[n * 65 + cidx] = Hg[(size_t)(n0 + n) * DD + c0 + cidx];
        }
        __syncthreads();
        float acc[4][4];
#pragma unroll
        for (int i = 0; i < 4; i++)
#pragma unroll
            for (int j = 0; j < 4; j++) acc[i][j] = 0.f;
#pragma unroll 4
        for (int nn = 0; nn < 32; nn++) {
            float av[4], bv[4];
#pragma unroll
            for (int i = 0; i < 4; i++) av[i] = sA[nn * 65 + ty + 16 * i];
#pragma unroll
            for (int j = 0; j < 4; j++) bv[j] = sB[nn * 65 + tx + 16 * j];
#pragma unroll
            for (int i = 0; i < 4; i++)
#pragma unroll
                for (int j = 0; j < 4; j++) acc[i][j] = fmaf(av[i], bv[j], acc[i][j]);
        }
#pragma unroll
        for (int i = 0; i < 4; i++)
#pragma unroll
            for (int j = 0; j < 4; j++) accd[i][j] += (double)acc[i][j];
        __syncthreads();
    }
    double* Bg = g_B64 + (size_t)g * DD * DD;
#pragma unroll
    for (int i = 0; i < 4; i++)
#pragma unroll
        for (int j = 0; j < 4; j++) {
            int gi = r0 + ty + 16 * i, gj = c0 + tx + 16 * j;
            double v = accd[i][j] - (gi == gj ? 1.0 : 0.0);
            Bg[(size_t)gi * DD + gj] = v;
            if (tile == 1) Bg[(size_t)gj * DD + gi] = v;
        }
}

// ---------------- deflation + normalization --------------------------------
__device__ __forceinline__ float redsum128(float x, float* sred, int t) {
    __syncthreads();
    sred[t] = x;
    __syncthreads();
    if (t < 64) sred[t] += sred[t + 64];
    __syncthreads();
    if (t < 32) {
        float v = sred[t] + sred[t + 32];
#pragma unroll
        for (int o = 16; o; o >>= 1) v += __shfl_xor_sync(0xffffffffu, v, o);
        if (t == 0) sred[0] = v;
    }
    __syncthreads();
    return sred[0];
}

__global__ void k_deflate() {
    extern __shared__ float sm[];
    float* Bs   = sm;               // 128*129
    float* sv   = sm + 128 * 129;
    float* su   = sv + 128;
    float* sred = su + 128;
    int g = blockIdx.x, t = threadIdx.x;
    const double* B64 = g_B64 + (size_t)g * DD * DD;

    for (int idx = t; idx < DD * DD; idx += 128)
        Bs[(idx >> 7) * 129 + (idx & 127)] = (float)B64[idx];
    sv[t] = 1.f;
    __syncthreads();

    float lam1 = 0.f;
    for (int it = 0; it < 14; it++) {
        float w = 0.f;
#pragma unroll 8
        for (int k = 0; k < 128; k++) w = fmaf(Bs[t * 129 + k], sv[k], w);
        lam1 = redsum128(sv[t] * w, sred, t);
        float ww = redsum128(w * w, sred, t);
        float inv = rsqrtf(ww + 1e-30f);
        __syncthreads();
        sv[t] = w * inv;
        __syncthreads();
    }

    su[t] = __sinf(0.9f * (float)t + 0.5f);
    __syncthreads();
    float lam2 = 0.f;
    for (int it = 0; it < 14; it++) {
        float s = redsum128(sv[t] * su[t], sred, t);
        float w = 0.f;
#pragma unroll 8
        for (int k = 0; k < 128; k++) w = fmaf(Bs[t * 129 + k], su[k], w);
        w -= lam1 * s * sv[t];
        lam2 = fabsf(redsum128(su[t] * w, sred, t));
        float ww = redsum128(w * w, sred, t);
        float inv = rsqrtf(ww + 1e-30f);
        __syncthreads();
        su[t] = w * inv;
        __syncthreads();
    }
    lam2 = fmaxf(lam2, 1e-2f);

    double dd  = (double)lam1 - 0.5 * (double)lam2;
    double inv = 1.0 / (1.10 * (double)lam2);
    float* X0 = g_X32a + (size_t)g * DD * DD;
    for (int idx = t; idx < DD * DD; idx += 128) {
        int i = idx >> 7, j = idx & 127;
        X0[idx] = (float)((B64[idx] - dd * (double)sv[i] * (double)sv[j]) * inv);
    }
}

// ---------------- symmetric batched GEMM: OUT = A*(alpha*I + beta*B) -------
// All iterates commute & are symmetric -> compute only upper 64x64 block-
// tiles {(0,0),(0,64),(64,64)}; tile 1 mirrors its transpose to (64,0).
// grid (3, NG), 64 threads, 8x8 acc per thread.
__global__ void k_bgemm_sym(const float* __restrict__ A, const float* __restrict__ B,
                            float* __restrict__ OUT, float alpha, float beta) {
    __shared__ float As[16 * 68];
    __shared__ float Ms[16 * 64];
    int g = blockIdx.y;
    int tile = blockIdx.x;
    int r0 = (tile == 2) ? 64 : 0;
    int c0 = (tile == 0) ? 0 : 64;
    size_t base = (size_t)g * DD * DD;
    const float* Ag = A + base;
    const float* Bg = B + base;
    int t = threadIdx.x, tx = t & 7, ty = t >> 3;
    float acc[8][8];
#pragma unroll
    for (int i = 0; i < 8; i++)
#pragma unroll
        for (int j = 0; j < 8; j++) acc[i][j] = 0.f;

    for (int k0 = 0; k0 < DD; k0 += 16) {
        // A tile: 64 rows x 16 k, stored transposed As[k][row]
#pragma unroll
        for (int ld = 0; ld < 4; ld++) {
            int l = t + ld * 64;
            int row = l >> 2, c4 = l & 3;
            float4 a = *(const float4*)(Ag + (size_t)(r0 + row) * DD + k0 + c4 * 4);
            As[(c4 * 4 + 0) * 68 + row] = a.x;
            As[(c4 * 4 + 1) * 68 + row] = a.y;
            As[(c4 * 4 + 2) * 68 + row] = a.z;
            As[(c4 * 4 + 3) * 68 + row] = a.w;
        }
        // M tile: 16 k x 64 cols, fused alpha*I + beta*B
#pragma unroll
        for (int ld = 0; ld < 4; ld++) {
            int l = t + ld * 64;
            int kr = l >> 4, n4 = l & 15;
            int gk = k0 + kr;
            float4 v = *(const float4*)(Bg + (size_t)gk * DD + c0 + n4 * 4);
            v.x *= beta; v.y *= beta; v.z *= beta; v.w *= beta;
            int dcol = gk - (c0 + n4 * 4);
            if (dcol >= 0 && dcol < 4) ((float*)&v)[dcol] += alpha;
            *(float4*)(Ms + kr * 64 + n4 * 4) = v;
        }
        __syncthreads();
#pragma unroll
        for (int kk = 0; kk < 16; kk++) {
            float av[8], bv[8];
            *(float4*)av       = *(float4*)(As + kk * 68 + ty * 8);
            *(float4*)(av + 4) = *(float4*)(As + kk * 68 + ty * 8 + 4);
            *(float4*)bv       = *(float4*)(Ms + kk * 64 + tx * 8);
            *(float4*)(bv + 4) = *(float4*)(Ms + kk * 64 + tx * 8 + 4);
#pragma unroll
            for (int i = 0; i < 8; i++)
#pragma unroll
                for (int j = 0; j < 8; j++) acc[i][j] = fmaf(av[i], bv[j], acc[i][j]);
        }
        __syncthreads();
    }
    float* Og = OUT + base;
#pragma unroll
    for (int i = 0; i < 8; i++) {
        int row = r0 + ty * 8 + i;
#pragma unroll
        for (int j4 = 0; j4 < 2; j4++) {
            float4 o;
            o.x = acc[i][j4 * 4 + 0]; o.y = acc[i][j4 * 4 + 1];
            o.z = acc[i][j4 * 4 + 2]; o.w = acc[i][j4 * 4 + 3];
            *(float4*)(Og + (size_t)row * DD + c0 + tx * 8 + j4 * 4) = o;
        }
    }
    if (tile == 1) {  // mirror transpose to (64,0)
#pragma unroll
        for (int j = 0; j < 8; j++) {
            int orow = c0 + tx * 8 + j;
#pragma unroll
            for (int i4 = 0; i4 < 2; i4++) {
                float4 o;
                o.x = acc[i4 * 4 + 0][j]; o.y = acc[i4 * 4 + 1][j];
                o.z = acc[i4 * 4 + 2][j]; o.w = acc[i4 * 4 + 3][j];
                *(float4*)(Og + (size_t)orow * DD + r0 + ty * 8 + i4 * 4) = o;
            }
        }
    }
}

// ---------------- pack projector -------------------------------------------
__global__ void k_pack(const float* __restrict__ X) {
    int g = blockIdx.x, t = threadIdx.x;
    const float* Xg = X + (size_t)g * DD * DD;
    float* Pg = g_pooled + (size_t)g * TRIU;
    for (int idx = t; idx < DD * DD; idx += 256) {
        int i = idx >> 7, j = idx & 127;
        if (j >= i)
            Pg[i * 128 - (i * (i - 1)) / 2 + (j - i)] =
                0.5f * Xg[idx] + (i == j ? 0.5f : 0.f);
    }
}

// ---------------- generic FC GEMM: 64x64 tile, split-K via grid.z ----------
__global__ void k_fc(const float* __restrict__ A, const float* __restrict__ B,
                     float* __restrict__ Cm, int M, int Nn, int K) {
    __shared__ float As[16 * 68];
    __shared__ float Bs[16 * 64];
    int t = threadIdx.x;
    int tx = t & 15, ty = t >> 4;
    int c0 = blockIdx.x * 64, r0 = blockIdx.y * 64;
    int klen = K / gridDim.z;
    int k0 = blockIdx.z * klen;
    float acc[4][4];
#pragma unroll
    for (int i = 0; i < 4; i++)
#pragma unroll
        for (int j = 0; j < 4; j++) acc[i][j] = 0.f;

    int arow = t >> 2, akq = t & 3;
    int bkk = t >> 4, bn4 = t & 15;
    for (int kb = 0; kb < klen; kb += 16) {
        float4 a = *(const float4*)(A + (size_t)(r0 + arow) * K + k0 + kb + akq * 4);
        As[(akq * 4 + 0) * 68 + arow] = a.x;
        As[(akq * 4 + 1) * 68 + arow] = a.y;
        As[(akq * 4 + 2) * 68 + arow] = a.z;
        As[(akq * 4 + 3) * 68 + arow] = a.w;
        *(float4*)(Bs + bkk * 64 + bn4 * 4) =
            *(const float4*)(B + (size_t)(k0 + kb + bkk) * Nn + c0 + bn4 * 4);
        __syncthreads();
#pragma unroll
        for (int kk = 0; kk < 16; kk++) {
            float av[4], bv[4];
            *(float4*)av = *(float4*)(As + kk * 68 + ty * 4);
            *(float4*)bv = *(float4*)(Bs + kk * 64 + tx * 4);
#pragma unroll
            for (int i = 0; i < 4; i++)
#pragma unroll
                for (int j = 0; j < 4; j++) acc[i][j] = fmaf(av[i], bv[j], acc[i][j]);
        }
        __syncthreads();
    }
#pragma unroll
    for (int i = 0; i < 4; i++)
#pragma unroll
        for (int j = 0; j < 4; j++)
            atomicAdd(&Cm[(size_t)(r0 + ty * 4 + i) * Nn + c0 + tx * 4 + j], acc[i][j]);
}

// ---------------- BN over G=256 rows ---------------------------------------
__global__ void k_bnrelu(float* __restrict__ Zm, const float* __restrict__ gg,
                         const float* __restrict__ bb, int Cc, int relu) {
    int c = blockIdx.x, t = threadIdx.x;
    int lane = t & 31, wid = t >> 5;
    __shared__ float a1[8], a2[8];
    float v = Zm[(size_t)t * Cc + c];
    float s1 = v, s2 = v * v;
#pragma unroll
    for (int o = 16; o; o >>= 1) {
        s1 += __shfl_xor_sync(0xffffffffu, s1, o);
        s2 += __shfl_xor_sync(0xffffffffu, s2, o);
    }
    if (lane == 0) { a1[wid] = s1; a2[wid] = s2; }
    __syncthreads();
    if (t == 0) {
        float m = 0.f, q = 0.f;
        for (int i = 0; i < 8; i++) { m += a1[i]; q += a2[i]; }
        m *= (1.f / 256.f);
        q = q * (1.f / 256.f) - m * m;
        a1[0] = m; a2[0] = rsqrtf(q + 1e-5f);
    }
    __syncthreads();
    float o = (v - a1[0]) * a2[0] * gg[c] + bb[c];
    if (relu) o = fmaxf(o, 0.f);
    Zm[(size_t)t * Cc + c] = o;
}

// ---------------- FC3 fused with final BN ----------------------------------
__global__ void k_fc3bn(const float* __restrict__ w3, const float* __restrict__ g3,
                        const float* __restrict__ be3, float* __restrict__ outp) {
    __shared__ float sc[256 * CLSN];
    __shared__ float mu[CLSN], rs[CLSN];
    int t = threadIdx.x;
    float acc[CLSN];
#pragma unroll
    for (int c = 0; c < CLSN; c++) acc[c] = 0.f;
    for (int k = 0; k < FC2N; k++) {
        float a = g_z2[(size_t)t * FC2N + k];
#pragma unroll
        for (int c = 0; c < CLSN; c++) acc[c] = fmaf(a, w3[k * CLSN + c], acc[c]);
    }
#pragma unroll
    for (int c = 0; c < CLSN; c++) sc[t * CLSN + c] = acc[c];
    __syncthreads();
    if (t < CLSN) {
        float m = 0.f, q = 0.f;
        for (int r = 0; r < 256; r++) {
            float v = sc[r * CLSN + t];
            m += v; q += v * v;
        }
        m *= (1.f / 256.f);
        q = q * (1.f / 256.f) - m * m;
        mu[t] = m;
        rs[t] = rsqrtf(q + 1e-5f) * g3[t];
    }
    __syncthreads();
#pragma unroll
    for (int c = 0; c < CLSN; c++)
        outp[t * CLSN + c] = (sc[t * CLSN + c] - mu[c]) * rs[c] + be3[c];
}

// ---------------- launch ----------------------------------------------------
extern "C" void kernel_launch(void* const* d_in, const int* in_sizes, int n_in,
                              void* d_out, int out_size) {
    const float* x    = (const float*)d_in[0];
    const int*   ei   = (const int*)d_in[3];
    const float* eps  = (const float*)d_in[4];
    const float* w0   = (const float*)d_in[5];
    const float* g0   = (const float*)d_in[7];
    const float* be0  = (const float*)d_in[8];
    const float* w1   = (const float*)d_in[9];
    const float* b1   = (const float*)d_in[10];
    const float* fw1  = (const float*)d_in[11];
    const float* fg1  = (const float*)d_in[13];
    const float* fbe1 = (const float*)d_in[14];
    const float* fw2  = (const float*)d_in[15];
    const float* fg2  = (const float*)d_in[17];
    const float* fbe2 = (const float*)d_in[18];
    const float* fw3  = (const float*)d_in[19];
    const float* fg3  = (const float*)d_in[21];
    const float* fbe3 = (const float*)d_in[22];

    float* hidden = (float*)d_out;
    float* score  = (float*)d_out + (size_t)N_NODES * DD;

    float *X32a, *X32b, *Y32, *T32, *dz1, *dz2, *dpool;
    cudaGetSymbolAddress((void**)&X32a, g_X32a);
    cudaGetSymbolAddress((void**)&X32b, g_X32b);
    cudaGetSymbolAddress((void**)&Y32, g_Y32);
    cudaGetSymbolAddress((void**)&T32, g_T32);
    cudaGetSymbolAddress((void**)&dz1, g_z1);
    cudaGetSymbolAddress((void**)&dz2, g_z2);
    cudaGetSymbolAddress((void**)&dpool, g_pooled);

    const int defl_smem = (128 * 129 + 3 * 128) * (int)sizeof(float);
    cudaFuncSetAttribute(k_deflate, cudaFuncAttributeMaxDynamicSharedMemorySize,
                         defl_smem);

    // --- GIN conv: CSR build + gather, GEMMs, BN ---
    k_init<<<512, 256>>>();
    k_hist<<<EE / 256, 256>>>(ei);
    k_scan<<<1, 1024>>>();
    k_scatter<<<EE / 256, 256>>>(ei);
    k_agg<<<N_NODES * 32 / 256, 256>>>(x, eps);
    k_gemm_nodes<0><<<N_NODES / 128, 256>>>(w0, nullptr, nullptr);
    k_stats<<<N_NODES / 256, 256>>>();
    k_bnfin<<<1, 128>>>(g0, be0);
    k_gemm_nodes<1><<<N_NODES / 128, 256>>>(w1, b1, hidden);

    // --- spectral projector: Gram -> deflate -> fp32 sign iteration ---
    k_gram<<<dim3(3, NG), 256>>>(hidden);
    k_deflate<<<NG, 128, defl_smem>>>();

    // 12 quintic + 4 cubic (R5/R7-proven schedule), Horner form, symmetric
    // tiles only. p(X) = X(aI + Z), Z = Y(bI + cY), Y = X^2.
    const float QA = 3.4445f, QB = -4.7750f, QC = 2.0315f;
    dim3 sg(3, NG);
    float* Xc = X32a; float* Xn = X32b;
    for (int it = 0; it < 12; it++) {
        k_bgemm_sym<<<sg, 64>>>(Xc, Xc, Y32, 0.f, 1.f);   // Y = X^2
        k_bgemm_sym<<<sg, 64>>>(Y32, Y32, T32, QB, QC);   // Z = bY + cY^2
        k_bgemm_sym<<<sg, 64>>>(Xc, T32, Xn, QA, 1.f);    // X' = aX + XZ
        float* tmp = Xc; Xc = Xn; Xn = tmp;
    }
    for (int it = 0; it < 4; it++) {
        k_bgemm_sym<<<sg, 64>>>(Xc, Xc, Y32, 0.f, 1.f);   // Y = X^2
        k_bgemm_sym<<<sg, 64>>>(Xc, Y32, Xn, 1.5f, -0.5f);// X' = 1.5X - 0.5XY
        float* tmp = Xc; Xc = Xn; Xn = tmp;
    }
    k_pack<<<NG, 256>>>(Xc);

    // --- FC head ---
    k_fc<<<dim3(FC1N / 64, NG / 64, 12), 256>>>(dpool, fw1, dz1, NG, FC1N, TRIU);
    k_bnrelu<<<FC1N, 256>>>(dz1, fg1, fbe1, FC1N, 1);
    k_fc<<<dim3(FC2N / 64, NG / 64, 1), 256>>>(dz1, fw2, dz2, NG, FC2N, FC1N);
    k_bnrelu<<<FC2N, 256>>>(dz2, fg2, fbe2, FC2N, 1);
    k_fc3bn<<<1, 256>>>(fw3, fg3, fbe3, score);
}